// round 1
// baseline (speedup 1.0000x reference)
#include <cuda_runtime.h>

// Problem constants
#define NN   20000      // nodes
#define NE   320000     // edges
#define NFD  128        // node feature dim
#define EFD  32         // edge feature dim
#define HH   256        // hidden
#define OUTD 128        // output dim
#define NL   4          // layers
#define NG   64         // graphs

// GEMM tiling
#define BM 128
#define BN 64
#define BK 16

// ---------------- scratch (no allocations allowed) ----------------
__device__ float g_h   [NN * HH];
__device__ float g_h2  [NN * HH];
__device__ float g_tmp [NN * HH];
__device__ float g_agg [NN * HH];
__device__ float g_M1  [(size_t)NE * HH];   // 327 MB message intermediate
__device__ float g_pool[NG * HH];
__device__ float g_cnt [NG];
__device__ float g_t1  [NG * HH];
__device__ int   g_is64;

// ---------------- helpers ----------------
__device__ __forceinline__ float4 ld4(const float* p) {
    return *reinterpret_cast<const float4*>(p);
}

// index buffers may be int32 or int64 (jax x64 ambiguity). We read as 32-bit
// words; for int64 (values < 2^31, non-negative) the low word at 2*i is the value.
__device__ __forceinline__ int ldidx(const int* w, int is64, long i) {
    return is64 ? w[2 * i] : w[(size_t)i];
}

// Detector: sample odd 32-bit words of edge_index within the first 2*NE words
// (valid range under BOTH interpretations). int64 -> high words, all zero.
// int32 -> genuine random node ids, essentially surely nonzero.
__global__ void k_detect(const int* __restrict__ w) {
    __shared__ int nz;
    if (threadIdx.x == 0) nz = 0;
    __syncthreads();
    int local = 0;
    for (int i = 1 + 2 * threadIdx.x; i < 2 * NE; i += 2 * 256) local |= w[i];
    if (local) atomicOr(&nz, 1);
    __syncthreads();
    if (threadIdx.x == 0) g_is64 = (nz == 0) ? 1 : 0;
}

// ---------------- generic node-level GEMM ----------------
// C[M,256] = act( [A1 | A2][M, K1+K2] @ W[K1+K2,256] + bias )
__global__ void k_node(const float* __restrict__ A1, int K1,
                       const float* __restrict__ A2, int K2,
                       const float* __restrict__ W,
                       const float* __restrict__ bias,
                       float* __restrict__ C,
                       int M, int doRelu)
{
    __shared__ float As[BK][BM];
    __shared__ float Bs[BK][BN];

    const int tid = threadIdx.x;
    const int tx = tid & 15;          // 0..15 -> 4 cols
    const int ty = tid >> 4;          // 0..15 -> 8 rows
    const int m0 = blockIdx.x * BM;
    const int n0 = blockIdx.y * BN;
    const int K  = K1 + K2;

    float acc[8][4];
#pragma unroll
    for (int i = 0; i < 8; i++)
#pragma unroll
        for (int j = 0; j < 4; j++) acc[i][j] = 0.f;

    for (int k0 = 0; k0 < K; k0 += BK) {
        // load B tile: 16x64 = 256 float4, one per thread
        {
            int kr = tid >> 4;
            int c4 = (tid & 15) * 4;
            float4 b = ld4(W + (size_t)(k0 + kr) * HH + n0 + c4);
            Bs[kr][c4 + 0] = b.x; Bs[kr][c4 + 1] = b.y;
            Bs[kr][c4 + 2] = b.z; Bs[kr][c4 + 3] = b.w;
        }
        // load A tile: 128x16 = 512 float4, two per thread, stored transposed
#pragma unroll
        for (int j = 0; j < 2; j++) {
            int v  = tid + 256 * j;
            int r  = v >> 2;
            int c4 = (v & 3) * 4;
            int gr = m0 + r;
            int gc = k0 + c4;
            float4 a = make_float4(0.f, 0.f, 0.f, 0.f);
            if (gr < M) {
                if (gc < K1) a = ld4(A1 + (size_t)gr * K1 + gc);
                else         a = ld4(A2 + (size_t)gr * K2 + (gc - K1));
            }
            As[c4 + 0][r] = a.x; As[c4 + 1][r] = a.y;
            As[c4 + 2][r] = a.z; As[c4 + 3][r] = a.w;
        }
        __syncthreads();
#pragma unroll
        for (int k = 0; k < BK; k++) {
            float4 a0 = *(const float4*)&As[k][ty * 8];
            float4 a1 = *(const float4*)&As[k][ty * 8 + 4];
            float4 b  = *(const float4*)&Bs[k][tx * 4];
            float av[8] = {a0.x, a0.y, a0.z, a0.w, a1.x, a1.y, a1.z, a1.w};
            float bv[4] = {b.x, b.y, b.z, b.w};
#pragma unroll
            for (int i = 0; i < 8; i++)
#pragma unroll
                for (int j = 0; j < 4; j++) acc[i][j] += av[i] * bv[j];
        }
        __syncthreads();
    }

    const float4 bv4 = ld4(bias + n0 + tx * 4);
    const float bb[4] = {bv4.x, bv4.y, bv4.z, bv4.w};
#pragma unroll
    for (int i = 0; i < 8; i++) {
        int gr = m0 + ty * 8 + i;
        if (gr < M) {
            float4 o;
            float v0 = acc[i][0] + bb[0];
            float v1 = acc[i][1] + bb[1];
            float v2 = acc[i][2] + bb[2];
            float v3 = acc[i][3] + bb[3];
            if (doRelu) {
                v0 = fmaxf(v0, 0.f); v1 = fmaxf(v1, 0.f);
                v2 = fmaxf(v2, 0.f); v3 = fmaxf(v3, 0.f);
            }
            o.x = v0; o.y = v1; o.z = v2; o.w = v3;
            *reinterpret_cast<float4*>(C + (size_t)gr * HH + n0 + tx * 4) = o;
        }
    }
}

// ---------------- edge message GEMM1 (fused gather) ----------------
// M1[E,256] = relu( [h[dst] | h[src] | edge_attr][E,544] @ W1 + b1 )
__global__ void k_edge_msg(const float* __restrict__ h,
                           const float* __restrict__ ea,
                           const int* __restrict__ eidx,
                           const float* __restrict__ W,
                           const float* __restrict__ bias,
                           float* __restrict__ out)
{
    __shared__ float As[BK][BM];
    __shared__ float Bs[BK][BN];
    __shared__ int sDst[BM];
    __shared__ int sSrc[BM];

    const int tid = threadIdx.x;
    const int tx = tid & 15;
    const int ty = tid >> 4;
    const int m0 = blockIdx.x * BM;     // edge tile (E divisible by 128)
    const int n0 = blockIdx.y * BN;
    const int is64 = g_is64;

    if (tid < BM) {
        sSrc[tid] = ldidx(eidx, is64, (long)m0 + tid);            // row 0 = src (x_j)
        sDst[tid] = ldidx(eidx, is64, (long)NE + m0 + tid);       // row 1 = dst (x_i)
    }
    __syncthreads();

    float acc[8][4];
#pragma unroll
    for (int i = 0; i < 8; i++)
#pragma unroll
        for (int j = 0; j < 4; j++) acc[i][j] = 0.f;

    for (int k0 = 0; k0 < 2 * HH + EFD; k0 += BK) {   // K = 544
        {
            int kr = tid >> 4;
            int c4 = (tid & 15) * 4;
            float4 b = ld4(W + (size_t)(k0 + kr) * HH + n0 + c4);
            Bs[kr][c4 + 0] = b.x; Bs[kr][c4 + 1] = b.y;
            Bs[kr][c4 + 2] = b.z; Bs[kr][c4 + 3] = b.w;
        }
#pragma unroll
        for (int j = 0; j < 2; j++) {
            int v  = tid + 256 * j;
            int r  = v >> 2;
            int c4 = (v & 3) * 4;
            int gc = k0 + c4;
            float4 a;
            if (gc < HH)           a = ld4(h  + (size_t)sDst[r] * HH + gc);          // x_i
            else if (gc < 2 * HH)  a = ld4(h  + (size_t)sSrc[r] * HH + (gc - HH));   // x_j
            else                   a = ld4(ea + (size_t)(m0 + r) * EFD + (gc - 2 * HH));
            As[c4 + 0][r] = a.x; As[c4 + 1][r] = a.y;
            As[c4 + 2][r] = a.z; As[c4 + 3][r] = a.w;
        }
        __syncthreads();
#pragma unroll
        for (int k = 0; k < BK; k++) {
            float4 a0 = *(const float4*)&As[k][ty * 8];
            float4 a1 = *(const float4*)&As[k][ty * 8 + 4];
            float4 b  = *(const float4*)&Bs[k][tx * 4];
            float av[8] = {a0.x, a0.y, a0.z, a0.w, a1.x, a1.y, a1.z, a1.w};
            float bv[4] = {b.x, b.y, b.z, b.w};
#pragma unroll
            for (int i = 0; i < 8; i++)
#pragma unroll
                for (int j = 0; j < 4; j++) acc[i][j] += av[i] * bv[j];
        }
        __syncthreads();
    }

    const float4 bv4 = ld4(bias + n0 + tx * 4);
#pragma unroll
    for (int i = 0; i < 8; i++) {
        int gr = m0 + ty * 8 + i;
        float4 o;
        o.x = fmaxf(acc[i][0] + bv4.x, 0.f);
        o.y = fmaxf(acc[i][1] + bv4.y, 0.f);
        o.z = fmaxf(acc[i][2] + bv4.z, 0.f);
        o.w = fmaxf(acc[i][3] + bv4.w, 0.f);
        *reinterpret_cast<float4*>(out + (size_t)gr * HH + n0 + tx * 4) = o;
    }
}

// ---------------- edge GEMM2 + fused scatter-add ----------------
// agg[dst[e]] += M1[e] @ W2 + b2
__global__ void k_edge_scatter(const float* __restrict__ M1,
                               const float* __restrict__ W,
                               const float* __restrict__ bias,
                               const int* __restrict__ eidx,
                               float* __restrict__ agg)
{
    __shared__ float As[BK][BM];
    __shared__ float Bs[BK][BN];
    __shared__ int sDst[BM];

    const int tid = threadIdx.x;
    const int tx = tid & 15;
    const int ty = tid >> 4;
    const int m0 = blockIdx.x * BM;
    const int n0 = blockIdx.y * BN;
    const int is64 = g_is64;

    if (tid < BM) sDst[tid] = ldidx(eidx, is64, (long)NE + m0 + tid);
    __syncthreads();

    float acc[8][4];
#pragma unroll
    for (int i = 0; i < 8; i++)
#pragma unroll
        for (int j = 0; j < 4; j++) acc[i][j] = 0.f;

    for (int k0 = 0; k0 < HH; k0 += BK) {
        {
            int kr = tid >> 4;
            int c4 = (tid & 15) * 4;
            float4 b = ld4(W + (size_t)(k0 + kr) * HH + n0 + c4);
            Bs[kr][c4 + 0] = b.x; Bs[kr][c4 + 1] = b.y;
            Bs[kr][c4 + 2] = b.z; Bs[kr][c4 + 3] = b.w;
        }
#pragma unroll
        for (int j = 0; j < 2; j++) {
            int v  = tid + 256 * j;
            int r  = v >> 2;
            int c4 = (v & 3) * 4;
            float4 a = ld4(M1 + (size_t)(m0 + r) * HH + k0 + c4);
            As[c4 + 0][r] = a.x; As[c4 + 1][r] = a.y;
            As[c4 + 2][r] = a.z; As[c4 + 3][r] = a.w;
        }
        __syncthreads();
#pragma unroll
        for (int k = 0; k < BK; k++) {
            float4 a0 = *(const float4*)&As[k][ty * 8];
            float4 a1 = *(const float4*)&As[k][ty * 8 + 4];
            float4 b  = *(const float4*)&Bs[k][tx * 4];
            float av[8] = {a0.x, a0.y, a0.z, a0.w, a1.x, a1.y, a1.z, a1.w};
            float bv[4] = {b.x, b.y, b.z, b.w};
#pragma unroll
            for (int i = 0; i < 8; i++)
#pragma unroll
                for (int j = 0; j < 4; j++) acc[i][j] += av[i] * bv[j];
        }
        __syncthreads();
    }

    const float4 bv4 = ld4(bias + n0 + tx * 4);
    const float bb[4] = {bv4.x, bv4.y, bv4.z, bv4.w};
#pragma unroll
    for (int i = 0; i < 8; i++) {
        int r = ty * 8 + i;
        int d = sDst[r];
        float* dst = agg + (size_t)d * HH + n0 + tx * 4;
#pragma unroll
        for (int j = 0; j < 4; j++)
            atomicAdd(dst + j, acc[i][j] + bb[j]);
    }
}

// ---------------- pooling ----------------
__global__ void k_pool(const float* __restrict__ h, const int* __restrict__ batch) {
    int idx = blockIdx.x * blockDim.x + threadIdx.x;
    if (idx >= NN * HH) return;
    int n = idx >> 8;           // /256
    int c = idx & 255;
    int g = ldidx(batch, g_is64, n);
    atomicAdd(&g_pool[g * HH + c], h[idx]);
    if (c == 0) atomicAdd(&g_cnt[g], 1.0f);
}

// ---------------- head ----------------
__global__ void k_head1(const float* __restrict__ hw1, const float* __restrict__ hb1) {
    __shared__ float p[HH];
    int g = blockIdx.x;
    int t = threadIdx.x;
    float cnt = fmaxf(g_cnt[g], 1.0f);
    p[t] = g_pool[g * HH + t] / cnt;
    __syncthreads();
    float s = hb1[t];
    for (int k = 0; k < HH; k++) s += p[k] * hw1[k * HH + t];
    g_t1[g * HH + t] = fmaxf(s, 0.f);
}

__global__ void k_head2(const float* __restrict__ hw2, const float* __restrict__ hb2,
                        float* __restrict__ out) {
    __shared__ float q[HH];
    int g = blockIdx.x;
    int t = threadIdx.x;   // 128 threads
    q[t] = g_t1[g * HH + t];
    q[t + 128] = g_t1[g * HH + t + 128];
    __syncthreads();
    float s = hb2[t];
    for (int k = 0; k < HH; k++) s += q[k] * hw2[k * OUTD + t];
    out[g * OUTD + t] = s;
}

// ---------------- launcher ----------------
extern "C" void kernel_launch(void* const* d_in, const int* in_sizes, int n_in,
                              void* d_out, int out_size)
{
    const float* x    = (const float*)d_in[0];
    const float* ea   = (const float*)d_in[1];
    const float* ew1  = (const float*)d_in[2];
    const float* eb1  = (const float*)d_in[3];
    const float* ew2  = (const float*)d_in[4];
    const float* eb2  = (const float*)d_in[5];
    const float* mw1  = (const float*)d_in[6];
    const float* mb1  = (const float*)d_in[7];
    const float* mw2  = (const float*)d_in[8];
    const float* mb2  = (const float*)d_in[9];
    const float* uw1  = (const float*)d_in[10];
    const float* ub1  = (const float*)d_in[11];
    const float* uw2  = (const float*)d_in[12];
    const float* ub2  = (const float*)d_in[13];
    const float* hw1  = (const float*)d_in[14];
    const float* hb1  = (const float*)d_in[15];
    const float* hw2  = (const float*)d_in[16];
    const float* hb2  = (const float*)d_in[17];
    const int*   eidx = (const int*)d_in[18];
    const int*   bat  = (const int*)d_in[19];
    float* out = (float*)d_out;

    void *p_h, *p_h2, *p_tmp, *p_agg, *p_M1, *p_pool, *p_cnt;
    cudaGetSymbolAddress(&p_h,    g_h);
    cudaGetSymbolAddress(&p_h2,   g_h2);
    cudaGetSymbolAddress(&p_tmp,  g_tmp);
    cudaGetSymbolAddress(&p_agg,  g_agg);
    cudaGetSymbolAddress(&p_M1,   g_M1);
    cudaGetSymbolAddress(&p_pool, g_pool);
    cudaGetSymbolAddress(&p_cnt,  g_cnt);

    k_detect<<<1, 256>>>(eidx);

    dim3 gNode((NN + BM - 1) / BM, HH / BN);   // 157 x 4
    dim3 gEdge(NE / BM, HH / BN);              // 2500 x 4

    // embedder
    k_node<<<gNode, 256>>>(x, NFD, (const float*)p_tmp, 0, ew1, eb1, (float*)p_tmp, NN, 1);
    k_node<<<gNode, 256>>>((const float*)p_tmp, HH, nullptr, 0, ew2, eb2, (float*)p_h, NN, 0);

    float* hc = (float*)p_h;
    float* hn = (float*)p_h2;

    for (int l = 0; l < NL; l++) {
        cudaMemsetAsync(p_agg, 0, (size_t)NN * HH * sizeof(float));
        k_edge_msg<<<gEdge, 256>>>(hc, ea, eidx,
                                   mw1 + (size_t)l * (2 * HH + EFD) * HH,
                                   mb1 + l * HH, (float*)p_M1);
        k_edge_scatter<<<gEdge, 256>>>((const float*)p_M1,
                                       mw2 + (size_t)l * HH * HH,
                                       mb2 + l * HH, eidx, (float*)p_agg);
        k_node<<<gNode, 256>>>(hc, HH, (const float*)p_agg, HH,
                               uw1 + (size_t)l * (2 * HH) * HH,
                               ub1 + l * HH, (float*)p_tmp, NN, 1);
        k_node<<<gNode, 256>>>((const float*)p_tmp, HH, nullptr, 0,
                               uw2 + (size_t)l * HH * HH,
                               ub2 + l * HH, hn, NN, 0);
        float* t = hc; hc = hn; hn = t;
    }

    cudaMemsetAsync(p_pool, 0, (size_t)NG * HH * sizeof(float));
    cudaMemsetAsync(p_cnt,  0, (size_t)NG * sizeof(float));
    k_pool<<<(NN * HH + 255) / 256, 256>>>(hc, bat);
    k_head1<<<NG, HH>>>(hw1, hb1);
    k_head2<<<NG, OUTD>>>(hw2, hb2, out);
}

// round 2
// speedup vs baseline: 2.5346x; 2.5346x over previous
#include <cuda_runtime.h>

// Problem constants
#define NN   20000
#define NE   320000
#define NFD  128
#define EFD  32
#define HH   256
#define OUTD 128
#define NL   4
#define NG   64

// GEMM tiling (tensor-core version)
#define BM 128
#define BN 128
#define BK 32
#define APAD 4      // As stride = BK+4 = 36
#define BPAD 8      // Bs stride = BN+8 = 136

// ---------------- scratch ----------------
__device__ float g_h   [NN * HH];
__device__ float g_h2  [NN * HH];
__device__ float g_tmp [NN * HH];
__device__ float g_agg [NN * HH];
__device__ float g_M1  [(size_t)NE * HH];
__device__ float g_pool[NG * HH];
__device__ float g_cnt [NG];
__device__ float g_t1  [NG * HH];
__device__ int   g_is64;

// ---------------- helpers ----------------
__device__ __forceinline__ float4 ld4(const float* p) {
    return *reinterpret_cast<const float4*>(p);
}

__device__ __forceinline__ unsigned f2tf(float f) {
    unsigned u;
    asm("cvt.rna.tf32.f32 %0, %1;" : "=r"(u) : "f"(f));
    return u;
}

__device__ __forceinline__ int ldidx(const int* w, int is64, long i) {
    return is64 ? w[2 * i] : w[(size_t)i];
}

__global__ void k_detect(const int* __restrict__ w) {
    __shared__ int nz;
    if (threadIdx.x == 0) nz = 0;
    __syncthreads();
    int local = 0;
    for (int i = 1 + 2 * threadIdx.x; i < 2 * NE; i += 2 * 256) local |= w[i];
    if (local) atomicOr(&nz, 1);
    __syncthreads();
    if (threadIdx.x == 0) g_is64 = (nz == 0) ? 1 : 0;
}

// m16n8k8 tf32 MMA
__device__ __forceinline__ void mma8(float* c, const unsigned* a, const unsigned* b) {
    asm volatile(
        "mma.sync.aligned.m16n8k8.row.col.f32.tf32.tf32.f32 "
        "{%0,%1,%2,%3},{%4,%5,%6,%7},{%8,%9},{%0,%1,%2,%3};"
        : "+f"(c[0]), "+f"(c[1]), "+f"(c[2]), "+f"(c[3])
        : "r"(a[0]), "r"(a[1]), "r"(a[2]), "r"(a[3]), "r"(b[0]), "r"(b[1]));
}

// Compute one BK=32 chunk: 4 k8 steps over the 64x32 warp tile (4x4 mma tiles)
__device__ __forceinline__ void mma_chunk(
    const unsigned As[BM][BK + APAD],
    const unsigned Bs[BK][BN + BPAD],
    float acc[4][4][4], int wm, int wn, int lane)
{
    const int r = lane >> 2;        // 0..7
    const int cc = lane & 3;        // 0..3
#pragma unroll
    for (int s = 0; s < 4; s++) {
        unsigned afr[4][4];
#pragma unroll
        for (int tm = 0; tm < 4; tm++) {
            int m = wm * 64 + tm * 16;
            afr[tm][0] = As[m + r    ][s * 8 + cc    ];
            afr[tm][1] = As[m + r + 8][s * 8 + cc    ];
            afr[tm][2] = As[m + r    ][s * 8 + cc + 4];
            afr[tm][3] = As[m + r + 8][s * 8 + cc + 4];
        }
        unsigned bfr[4][2];
#pragma unroll
        for (int tn = 0; tn < 4; tn++) {
            int n = wn * 32 + tn * 8;
            bfr[tn][0] = Bs[s * 8 + cc    ][n + r];
            bfr[tn][1] = Bs[s * 8 + cc + 4][n + r];
        }
#pragma unroll
        for (int tm = 0; tm < 4; tm++)
#pragma unroll
            for (int tn = 0; tn < 4; tn++)
                mma8(acc[tm][tn], afr[tm], bfr[tn]);
    }
}

// load B chunk: rows k0..k0+31 of W[K x 256], cols n0..n0+127
__device__ __forceinline__ void load_B(
    unsigned Bs[BK][BN + BPAD], const float* __restrict__ W,
    int k0, int n0, int tid)
{
#pragma unroll
    for (int j = 0; j < 4; j++) {
        int v = tid + 256 * j;          // 0..1023
        int r = v >> 5;                 // 0..31
        int c4 = (v & 31) * 4;          // 0..124
        float4 b = ld4(W + (size_t)(k0 + r) * HH + n0 + c4);
        Bs[r][c4 + 0] = f2tf(b.x);
        Bs[r][c4 + 1] = f2tf(b.y);
        Bs[r][c4 + 2] = f2tf(b.z);
        Bs[r][c4 + 3] = f2tf(b.w);
    }
}

// ---------------- edge message GEMM1 (fused gather, tf32 mma) ----------------
// M1[E,256] = relu( [h[dst] | h[src] | edge_attr][E,544] @ W1 + b1 )
__global__ void __launch_bounds__(256, 2)
k_edge_msg(const float* __restrict__ h,
           const float* __restrict__ ea,
           const int* __restrict__ eidx,
           const float* __restrict__ W,
           const float* __restrict__ bias,
           float* __restrict__ out)
{
    __shared__ unsigned As[BM][BK + APAD];
    __shared__ unsigned Bs[BK][BN + BPAD];
    __shared__ int sDst[BM];
    __shared__ int sSrc[BM];

    const int tid  = threadIdx.x;
    const int lane = tid & 31;
    const int warp = tid >> 5;
    const int wm = warp & 1;
    const int wn = warp >> 1;
    const int m0 = blockIdx.x * BM;
    const int n0 = blockIdx.y * BN;
    const int is64 = g_is64;

    if (tid < BM) {
        sSrc[tid] = ldidx(eidx, is64, (long)m0 + tid);        // x_j
        sDst[tid] = ldidx(eidx, is64, (long)NE + m0 + tid);   // x_i
    }
    __syncthreads();

    float acc[4][4][4];
#pragma unroll
    for (int a = 0; a < 4; a++)
#pragma unroll
        for (int b = 0; b < 4; b++)
#pragma unroll
            for (int c = 0; c < 4; c++) acc[a][b][c] = 0.f;

    for (int ch = 0; ch < 17; ch++) {       // K = 544 = 17*32
        load_B(Bs, W, ch * 32, n0, tid);
#pragma unroll
        for (int j = 0; j < 4; j++) {
            int v = tid + 256 * j;
            int r = v >> 3;
            int c4 = (v & 7) * 4;
            const float* p;
            if (ch < 8)       p = h  + (size_t)sDst[r] * HH + ch * 32 + c4;
            else if (ch < 16) p = h  + (size_t)sSrc[r] * HH + (ch - 8) * 32 + c4;
            else              p = ea + (size_t)(m0 + r) * EFD + c4;
            float4 a = ld4(p);
            As[r][c4 + 0] = f2tf(a.x);
            As[r][c4 + 1] = f2tf(a.y);
            As[r][c4 + 2] = f2tf(a.z);
            As[r][c4 + 3] = f2tf(a.w);
        }
        __syncthreads();
        mma_chunk(As, Bs, acc, wm, wn, lane);
        __syncthreads();
    }

    // epilogue: bias + relu, float2 stores
#pragma unroll
    for (int tm = 0; tm < 4; tm++) {
#pragma unroll
        for (int tn = 0; tn < 4; tn++) {
            int mr = m0 + wm * 64 + tm * 16 + (lane >> 2);
            int nc = n0 + wn * 32 + tn * 8 + 2 * (lane & 3);
            float b0 = bias[nc], b1 = bias[nc + 1];
            float2 o0, o1;
            o0.x = fmaxf(acc[tm][tn][0] + b0, 0.f);
            o0.y = fmaxf(acc[tm][tn][1] + b1, 0.f);
            o1.x = fmaxf(acc[tm][tn][2] + b0, 0.f);
            o1.y = fmaxf(acc[tm][tn][3] + b1, 0.f);
            *reinterpret_cast<float2*>(out + (size_t)mr * HH + nc) = o0;
            *reinterpret_cast<float2*>(out + (size_t)(mr + 8) * HH + nc) = o1;
        }
    }
}

// ---------------- edge GEMM2 + fused scatter-add (tf32 mma) ----------------
__global__ void __launch_bounds__(256, 2)
k_edge_scatter(const float* __restrict__ M1,
               const float* __restrict__ W,
               const float* __restrict__ bias,
               const int* __restrict__ eidx,
               float* __restrict__ agg)
{
    __shared__ unsigned As[BM][BK + APAD];
    __shared__ unsigned Bs[BK][BN + BPAD];
    __shared__ int sDst[BM];

    const int tid  = threadIdx.x;
    const int lane = tid & 31;
    const int warp = tid >> 5;
    const int wm = warp & 1;
    const int wn = warp >> 1;
    const int m0 = blockIdx.x * BM;
    const int n0 = blockIdx.y * BN;
    const int is64 = g_is64;

    if (tid < BM) sDst[tid] = ldidx(eidx, is64, (long)NE + m0 + tid);
    __syncthreads();

    float acc[4][4][4];
#pragma unroll
    for (int a = 0; a < 4; a++)
#pragma unroll
        for (int b = 0; b < 4; b++)
#pragma unroll
            for (int c = 0; c < 4; c++) acc[a][b][c] = 0.f;

    for (int ch = 0; ch < 8; ch++) {        // K = 256
        load_B(Bs, W, ch * 32, n0, tid);
#pragma unroll
        for (int j = 0; j < 4; j++) {
            int v = tid + 256 * j;
            int r = v >> 3;
            int c4 = (v & 7) * 4;
            float4 a = ld4(M1 + (size_t)(m0 + r) * HH + ch * 32 + c4);
            As[r][c4 + 0] = f2tf(a.x);
            As[r][c4 + 1] = f2tf(a.y);
            As[r][c4 + 2] = f2tf(a.z);
            As[r][c4 + 3] = f2tf(a.w);
        }
        __syncthreads();
        mma_chunk(As, Bs, acc, wm, wn, lane);
        __syncthreads();
    }

#pragma unroll
    for (int tm = 0; tm < 4; tm++) {
        int rl0 = wm * 64 + tm * 16 + (lane >> 2);
        int d0 = sDst[rl0];
        int d1 = sDst[rl0 + 8];
#pragma unroll
        for (int tn = 0; tn < 4; tn++) {
            int nc = n0 + wn * 32 + tn * 8 + 2 * (lane & 3);
            float b0 = bias[nc], b1 = bias[nc + 1];
            atomicAdd(agg + (size_t)d0 * HH + nc,     acc[tm][tn][0] + b0);
            atomicAdd(agg + (size_t)d0 * HH + nc + 1, acc[tm][tn][1] + b1);
            atomicAdd(agg + (size_t)d1 * HH + nc,     acc[tm][tn][2] + b0);
            atomicAdd(agg + (size_t)d1 * HH + nc + 1, acc[tm][tn][3] + b1);
        }
    }
}

// ---------------- node-level GEMM (concat A1|A2, tf32 mma) ----------------
__global__ void __launch_bounds__(256, 2)
k_node(const float* __restrict__ A1, int K1,
       const float* __restrict__ A2, int K2,
       const float* __restrict__ W,
       const float* __restrict__ bias,
       float* __restrict__ C,
       int M, int doRelu)
{
    __shared__ unsigned As[BM][BK + APAD];
    __shared__ unsigned Bs[BK][BN + BPAD];

    const int tid  = threadIdx.x;
    const int lane = tid & 31;
    const int warp = tid >> 5;
    const int wm = warp & 1;
    const int wn = warp >> 1;
    const int m0 = blockIdx.x * BM;
    const int n0 = blockIdx.y * BN;
    const int K  = K1 + K2;

    float acc[4][4][4];
#pragma unroll
    for (int a = 0; a < 4; a++)
#pragma unroll
        for (int b = 0; b < 4; b++)
#pragma unroll
            for (int c = 0; c < 4; c++) acc[a][b][c] = 0.f;

    for (int k0 = 0; k0 < K; k0 += BK) {
        load_B(Bs, W, k0, n0, tid);
#pragma unroll
        for (int j = 0; j < 4; j++) {
            int v = tid + 256 * j;
            int r = v >> 3;
            int c4 = (v & 7) * 4;
            int gr = m0 + r;
            float4 a = make_float4(0.f, 0.f, 0.f, 0.f);
            if (gr < M) {
                int gc = k0 + c4;
                if (gc < K1) a = ld4(A1 + (size_t)gr * K1 + gc);
                else         a = ld4(A2 + (size_t)gr * K2 + (gc - K1));
            }
            As[r][c4 + 0] = f2tf(a.x);
            As[r][c4 + 1] = f2tf(a.y);
            As[r][c4 + 2] = f2tf(a.z);
            As[r][c4 + 3] = f2tf(a.w);
        }
        __syncthreads();
        mma_chunk(As, Bs, acc, wm, wn, lane);
        __syncthreads();
    }

#pragma unroll
    for (int tm = 0; tm < 4; tm++) {
#pragma unroll
        for (int tn = 0; tn < 4; tn++) {
            int mr = m0 + wm * 64 + tm * 16 + (lane >> 2);
            int nc = n0 + wn * 32 + tn * 8 + 2 * (lane & 3);
            float b0 = bias[nc], b1 = bias[nc + 1];
            float v0 = acc[tm][tn][0] + b0;
            float v1 = acc[tm][tn][1] + b1;
            float v2 = acc[tm][tn][2] + b0;
            float v3 = acc[tm][tn][3] + b1;
            if (doRelu) {
                v0 = fmaxf(v0, 0.f); v1 = fmaxf(v1, 0.f);
                v2 = fmaxf(v2, 0.f); v3 = fmaxf(v3, 0.f);
            }
            if (mr < M) {
                float2 o; o.x = v0; o.y = v1;
                *reinterpret_cast<float2*>(C + (size_t)mr * HH + nc) = o;
            }
            if (mr + 8 < M) {
                float2 o; o.x = v2; o.y = v3;
                *reinterpret_cast<float2*>(C + (size_t)(mr + 8) * HH + nc) = o;
            }
        }
    }
}

// ---------------- pooling ----------------
__global__ void k_pool(const float* __restrict__ h, const int* __restrict__ batch) {
    int idx = blockIdx.x * blockDim.x + threadIdx.x;
    if (idx >= NN * HH) return;
    int n = idx >> 8;
    int c = idx & 255;
    int g = ldidx(batch, g_is64, n);
    atomicAdd(&g_pool[g * HH + c], h[idx]);
    if (c == 0) atomicAdd(&g_cnt[g], 1.0f);
}

// ---------------- head (tiny, scalar fp32) ----------------
__global__ void k_head1(const float* __restrict__ hw1, const float* __restrict__ hb1) {
    __shared__ float p[HH];
    int g = blockIdx.x;
    int t = threadIdx.x;
    float cnt = fmaxf(g_cnt[g], 1.0f);
    p[t] = g_pool[g * HH + t] / cnt;
    __syncthreads();
    float s = hb1[t];
    for (int k = 0; k < HH; k++) s += p[k] * hw1[k * HH + t];
    g_t1[g * HH + t] = fmaxf(s, 0.f);
}

__global__ void k_head2(const float* __restrict__ hw2, const float* __restrict__ hb2,
                        float* __restrict__ out) {
    __shared__ float q[HH];
    int g = blockIdx.x;
    int t = threadIdx.x;
    q[t] = g_t1[g * HH + t];
    q[t + 128] = g_t1[g * HH + t + 128];
    __syncthreads();
    float s = hb2[t];
    for (int k = 0; k < HH; k++) s += q[k] * hw2[k * OUTD + t];
    out[g * OUTD + t] = s;
}

// ---------------- launcher ----------------
extern "C" void kernel_launch(void* const* d_in, const int* in_sizes, int n_in,
                              void* d_out, int out_size)
{
    const float* x    = (const float*)d_in[0];
    const float* ea   = (const float*)d_in[1];
    const float* ew1  = (const float*)d_in[2];
    const float* eb1  = (const float*)d_in[3];
    const float* ew2  = (const float*)d_in[4];
    const float* eb2  = (const float*)d_in[5];
    const float* mw1  = (const float*)d_in[6];
    const float* mb1  = (const float*)d_in[7];
    const float* mw2  = (const float*)d_in[8];
    const float* mb2  = (const float*)d_in[9];
    const float* uw1  = (const float*)d_in[10];
    const float* ub1  = (const float*)d_in[11];
    const float* uw2  = (const float*)d_in[12];
    const float* ub2  = (const float*)d_in[13];
    const float* hw1  = (const float*)d_in[14];
    const float* hb1  = (const float*)d_in[15];
    const float* hw2  = (const float*)d_in[16];
    const float* hb2  = (const float*)d_in[17];
    const int*   eidx = (const int*)d_in[18];
    const int*   bat  = (const int*)d_in[19];
    float* out = (float*)d_out;

    void *p_h, *p_h2, *p_tmp, *p_agg, *p_M1, *p_pool, *p_cnt;
    cudaGetSymbolAddress(&p_h,    g_h);
    cudaGetSymbolAddress(&p_h2,   g_h2);
    cudaGetSymbolAddress(&p_tmp,  g_tmp);
    cudaGetSymbolAddress(&p_agg,  g_agg);
    cudaGetSymbolAddress(&p_M1,   g_M1);
    cudaGetSymbolAddress(&p_pool, g_pool);
    cudaGetSymbolAddress(&p_cnt,  g_cnt);

    k_detect<<<1, 256>>>(eidx);

    dim3 gNode((NN + BM - 1) / BM, HH / BN);   // 157 x 2
    dim3 gEdge(NE / BM, HH / BN);              // 2500 x 2

    // embedder
    k_node<<<gNode, 256>>>(x, NFD, nullptr, 0, ew1, eb1, (float*)p_tmp, NN, 1);
    k_node<<<gNode, 256>>>((const float*)p_tmp, HH, nullptr, 0, ew2, eb2, (float*)p_h, NN, 0);

    float* hc = (float*)p_h;
    float* hn = (float*)p_h2;

    for (int l = 0; l < NL; l++) {
        cudaMemsetAsync(p_agg, 0, (size_t)NN * HH * sizeof(float));
        k_edge_msg<<<gEdge, 256>>>(hc, ea, eidx,
                                   mw1 + (size_t)l * (2 * HH + EFD) * HH,
                                   mb1 + l * HH, (float*)p_M1);
        k_edge_scatter<<<gEdge, 256>>>((const float*)p_M1,
                                       mw2 + (size_t)l * HH * HH,
                                       mb2 + l * HH, eidx, (float*)p_agg);
        k_node<<<gNode, 256>>>(hc, HH, (const float*)p_agg, HH,
                               uw1 + (size_t)l * (2 * HH) * HH,
                               ub1 + l * HH, (float*)p_tmp, NN, 1);
        k_node<<<gNode, 256>>>((const float*)p_tmp, HH, nullptr, 0,
                               uw2 + (size_t)l * HH * HH,
                               ub2 + l * HH, hn, NN, 0);
        float* t = hc; hc = hn; hn = t;
    }

    cudaMemsetAsync(p_pool, 0, (size_t)NG * HH * sizeof(float));
    cudaMemsetAsync(p_cnt,  0, (size_t)NG * sizeof(float));
    k_pool<<<(NN * HH + 255) / 256, 256>>>(hc, bat);
    k_head1<<<NG, HH>>>(hw1, hb1);
    k_head2<<<NG, OUTD>>>(hw2, hb2, out);
}

// round 3
// speedup vs baseline: 2.8477x; 1.1236x over previous
#include <cuda_runtime.h>

// Problem constants
#define NN   20000
#define NE   320000
#define NFD  128
#define EFD  32
#define HH   256
#define OUTD 128
#define NL   4
#define NG   64

// GEMM tiling
#define BM 128
#define BN 128
#define BK 32
#define APAD 4
#define BPAD 8
#define ASTRIDE (BK + APAD)          // 36
#define BSTRIDE (BN + BPAD)          // 136
#define ASZ (BM * ASTRIDE)           // 4608 u32
#define BSZ (BK * BSTRIDE)           // 4352 u32
#define SMEM_BYTES ((2 * ASZ + 2 * BSZ) * 4)   // 71680

// ---------------- scratch ----------------
__device__ float g_h   [NN * HH];
__device__ float g_h2  [NN * HH];
__device__ float g_tmp [NN * HH];
__device__ float g_agg [NN * HH];
__device__ float g_M1  [(size_t)NE * HH];
__device__ float g_x32 [NN * NFD];
__device__ float g_ea32[(size_t)NE * EFD];
__device__ float g_w32 [1703936];
__device__ float g_pool[NG * HH];
__device__ float g_cnt [NG];
__device__ float g_t1  [NG * HH];
__device__ int   g_is64;

// weight offsets inside g_w32
#define OFF_EW1 0
#define OFF_EW2 32768
#define OFF_MW1 98304
#define MW1_STRIDE 139264
#define OFF_MW2 655360
#define MW2_STRIDE 65536
#define OFF_UW1 917504
#define UW1_STRIDE 131072
#define OFF_UW2 1441792
#define UW2_STRIDE 65536

// ---------------- helpers ----------------
__device__ __forceinline__ unsigned f2tf(float f) {
    unsigned u;
    asm("cvt.rna.tf32.f32 %0, %1;" : "=r"(u) : "f"(f));
    return u;
}

__device__ __forceinline__ void cpa16(unsigned* dst, const float* src) {
    unsigned d = (unsigned)__cvta_generic_to_shared(dst);
    asm volatile("cp.async.ca.shared.global [%0], [%1], 16;" :: "r"(d), "l"(src));
}
__device__ __forceinline__ void cpa16cg(unsigned* dst, const float* src) {
    unsigned d = (unsigned)__cvta_generic_to_shared(dst);
    asm volatile("cp.async.cg.shared.global [%0], [%1], 16;" :: "r"(d), "l"(src));
}
#define CP_COMMIT asm volatile("cp.async.commit_group;")
#define CP_WAIT1  asm volatile("cp.async.wait_group 1;")

__device__ __forceinline__ int ldidx(const int* w, int is64, long i) {
    return is64 ? w[2 * i] : w[(size_t)i];
}

__global__ void k_detect(const int* __restrict__ w) {
    __shared__ int nz;
    if (threadIdx.x == 0) nz = 0;
    __syncthreads();
    int local = 0;
    for (int i = 1 + 2 * threadIdx.x; i < 2 * NE; i += 2 * 256) local |= w[i];
    if (local) atomicOr(&nz, 1);
    __syncthreads();
    if (threadIdx.x == 0) g_is64 = (nz == 0) ? 1 : 0;
}

// elementwise tf32 rounding (vectorized), in-place safe
__global__ void k_cvt4(const float4* __restrict__ in, float4* __restrict__ out, int n4) {
    int i = blockIdx.x * blockDim.x + threadIdx.x;
    if (i < n4) {
        float4 v = in[i];
        v.x = __uint_as_float(f2tf(v.x));
        v.y = __uint_as_float(f2tf(v.y));
        v.z = __uint_as_float(f2tf(v.z));
        v.w = __uint_as_float(f2tf(v.w));
        out[i] = v;
    }
}

// m16n8k8 tf32 MMA
__device__ __forceinline__ void mma8(float* c, const unsigned* a, const unsigned* b) {
    asm volatile(
        "mma.sync.aligned.m16n8k8.row.col.f32.tf32.tf32.f32 "
        "{%0,%1,%2,%3},{%4,%5,%6,%7},{%8,%9},{%0,%1,%2,%3};"
        : "+f"(c[0]), "+f"(c[1]), "+f"(c[2]), "+f"(c[3])
        : "r"(a[0]), "r"(a[1]), "r"(a[2]), "r"(a[3]), "r"(b[0]), "r"(b[1]));
}

__device__ __forceinline__ void mma_chunk(
    const unsigned* __restrict__ As, const unsigned* __restrict__ Bs,
    float acc[4][4][4], int wm, int wn, int lane)
{
    const int r = lane >> 2;
    const int cc = lane & 3;
#pragma unroll
    for (int s = 0; s < 4; s++) {
        unsigned afr[4][4];
#pragma unroll
        for (int tm = 0; tm < 4; tm++) {
            int m = wm * 64 + tm * 16;
            const unsigned* a0 = As + (m + r) * ASTRIDE + s * 8 + cc;
            afr[tm][0] = a0[0];
            afr[tm][1] = a0[8 * ASTRIDE];
            afr[tm][2] = a0[4];
            afr[tm][3] = a0[8 * ASTRIDE + 4];
        }
        unsigned bfr[4][2];
#pragma unroll
        for (int tn = 0; tn < 4; tn++) {
            const unsigned* b0 = Bs + (s * 8 + cc) * BSTRIDE + wn * 32 + tn * 8 + r;
            bfr[tn][0] = b0[0];
            bfr[tn][1] = b0[4 * BSTRIDE];
        }
#pragma unroll
        for (int tm = 0; tm < 4; tm++)
#pragma unroll
            for (int tn = 0; tn < 4; tn++)
                mma8(acc[tm][tn], afr[tm], bfr[tn]);
    }
}

__device__ __forceinline__ void fill_B(unsigned* Bs, const float* __restrict__ W,
                                       int k0, int n0, int tid) {
#pragma unroll
    for (int j = 0; j < 4; j++) {
        int v = tid + 256 * j;
        int r = v >> 5;
        int c4 = (v & 31) * 4;
        cpa16(Bs + r * BSTRIDE + c4, W + (size_t)(k0 + r) * HH + n0 + c4);
    }
}

// ---------------- edge message GEMM1 ----------------
__global__ void __launch_bounds__(256, 2)
k_edge_msg(const float* __restrict__ h,
           const float* __restrict__ ea,
           const int* __restrict__ eidx,
           const float* __restrict__ W,
           const float* __restrict__ bias,
           float* __restrict__ out)
{
    extern __shared__ unsigned dsm[];
    unsigned* Asb[2] = { dsm, dsm + ASZ };
    unsigned* Bsb[2] = { dsm + 2 * ASZ, dsm + 2 * ASZ + BSZ };
    __shared__ int sDst[BM];
    __shared__ int sSrc[BM];

    const int tid  = threadIdx.x;
    const int lane = tid & 31;
    const int warp = tid >> 5;
    const int wm = warp & 1;
    const int wn = warp >> 1;
    const int m0 = blockIdx.x * BM;
    const int n0 = blockIdx.y * BN;
    const int is64 = g_is64;

    if (tid < BM) {
        sSrc[tid] = ldidx(eidx, is64, (long)m0 + tid);
        sDst[tid] = ldidx(eidx, is64, (long)NE + m0 + tid);
    }
    __syncthreads();

    float acc[4][4][4];
#pragma unroll
    for (int a = 0; a < 4; a++)
#pragma unroll
        for (int b = 0; b < 4; b++)
#pragma unroll
            for (int c = 0; c < 4; c++) acc[a][b][c] = 0.f;

    // fill for chunk ch into stage buffers
    auto fillA = [&](unsigned* As, int ch) {
#pragma unroll
        for (int j = 0; j < 4; j++) {
            int v = tid + 256 * j;
            int r = v >> 3;
            int c4 = (v & 7) * 4;
            const float* p;
            if (ch < 8)       p = h  + (size_t)sDst[r] * HH + ch * 32 + c4;
            else if (ch < 16) p = h  + (size_t)sSrc[r] * HH + (ch - 8) * 32 + c4;
            else              p = ea + (size_t)(m0 + r) * EFD + c4;
            cpa16(As + r * ASTRIDE + c4, p);
        }
    };

    fillA(Asb[0], 0);
    fill_B(Bsb[0], W, 0, n0, tid);
    CP_COMMIT;

#pragma unroll 1
    for (int ch = 0; ch < 17; ch++) {
        int cur = ch & 1, nxt = cur ^ 1;
        if (ch < 16) {
            fillA(Asb[nxt], ch + 1);
            fill_B(Bsb[nxt], W, (ch + 1) * 32, n0, tid);
        }
        CP_COMMIT;
        CP_WAIT1;
        __syncthreads();
        mma_chunk(Asb[cur], Bsb[cur], acc, wm, wn, lane);
        __syncthreads();
    }

#pragma unroll
    for (int tm = 0; tm < 4; tm++) {
#pragma unroll
        for (int tn = 0; tn < 4; tn++) {
            int mr = m0 + wm * 64 + tm * 16 + (lane >> 2);
            int nc = n0 + wn * 32 + tn * 8 + 2 * (lane & 3);
            float b0 = bias[nc], b1 = bias[nc + 1];
            float2 o0, o1;
            o0.x = __uint_as_float(f2tf(fmaxf(acc[tm][tn][0] + b0, 0.f)));
            o0.y = __uint_as_float(f2tf(fmaxf(acc[tm][tn][1] + b1, 0.f)));
            o1.x = __uint_as_float(f2tf(fmaxf(acc[tm][tn][2] + b0, 0.f)));
            o1.y = __uint_as_float(f2tf(fmaxf(acc[tm][tn][3] + b1, 0.f)));
            *reinterpret_cast<float2*>(out + (size_t)mr * HH + nc) = o0;
            *reinterpret_cast<float2*>(out + (size_t)(mr + 8) * HH + nc) = o1;
        }
    }
}

// ---------------- edge GEMM2 + fused scatter-add ----------------
__global__ void __launch_bounds__(256, 2)
k_edge_scatter(const float* __restrict__ M1,
               const float* __restrict__ W,
               const float* __restrict__ bias,
               const int* __restrict__ eidx,
               float* __restrict__ agg)
{
    extern __shared__ unsigned dsm[];
    unsigned* Asb[2] = { dsm, dsm + ASZ };
    unsigned* Bsb[2] = { dsm + 2 * ASZ, dsm + 2 * ASZ + BSZ };
    __shared__ int sDst[BM];

    const int tid  = threadIdx.x;
    const int lane = tid & 31;
    const int warp = tid >> 5;
    const int wm = warp & 1;
    const int wn = warp >> 1;
    const int m0 = blockIdx.x * BM;
    const int n0 = blockIdx.y * BN;
    const int is64 = g_is64;

    if (tid < BM) sDst[tid] = ldidx(eidx, is64, (long)NE + m0 + tid);
    __syncthreads();

    float acc[4][4][4];
#pragma unroll
    for (int a = 0; a < 4; a++)
#pragma unroll
        for (int b = 0; b < 4; b++)
#pragma unroll
            for (int c = 0; c < 4; c++) acc[a][b][c] = 0.f;

    auto fillA = [&](unsigned* As, int ch) {
#pragma unroll
        for (int j = 0; j < 4; j++) {
            int v = tid + 256 * j;
            int r = v >> 3;
            int c4 = (v & 7) * 4;
            cpa16cg(As + r * ASTRIDE + c4, M1 + (size_t)(m0 + r) * HH + ch * 32 + c4);
        }
    };

    fillA(Asb[0], 0);
    fill_B(Bsb[0], W, 0, n0, tid);
    CP_COMMIT;

#pragma unroll 1
    for (int ch = 0; ch < 8; ch++) {
        int cur = ch & 1, nxt = cur ^ 1;
        if (ch < 7) {
            fillA(Asb[nxt], ch + 1);
            fill_B(Bsb[nxt], W, (ch + 1) * 32, n0, tid);
        }
        CP_COMMIT;
        CP_WAIT1;
        __syncthreads();
        mma_chunk(Asb[cur], Bsb[cur], acc, wm, wn, lane);
        __syncthreads();
    }

#pragma unroll
    for (int tm = 0; tm < 4; tm++) {
        int rl0 = wm * 64 + tm * 16 + (lane >> 2);
        int d0 = sDst[rl0];
        int d1 = sDst[rl0 + 8];
#pragma unroll
        for (int tn = 0; tn < 4; tn++) {
            int nc = n0 + wn * 32 + tn * 8 + 2 * (lane & 3);
            float b0 = bias[nc], b1 = bias[nc + 1];
            atomicAdd(agg + (size_t)d0 * HH + nc,     acc[tm][tn][0] + b0);
            atomicAdd(agg + (size_t)d0 * HH + nc + 1, acc[tm][tn][1] + b1);
            atomicAdd(agg + (size_t)d1 * HH + nc,     acc[tm][tn][2] + b0);
            atomicAdd(agg + (size_t)d1 * HH + nc + 1, acc[tm][tn][3] + b1);
        }
    }
}

// ---------------- node-level GEMM (concat A1|A2) ----------------
__global__ void __launch_bounds__(256, 2)
k_node(const float* __restrict__ A1, int K1,
       const float* __restrict__ A2, int K2,
       const float* __restrict__ W,
       const float* __restrict__ bias,
       float* __restrict__ C,
       int M, int doRelu)
{
    extern __shared__ unsigned dsm[];
    unsigned* Asb[2] = { dsm, dsm + ASZ };
    unsigned* Bsb[2] = { dsm + 2 * ASZ, dsm + 2 * ASZ + BSZ };

    const int tid  = threadIdx.x;
    const int lane = tid & 31;
    const int warp = tid >> 5;
    const int wm = warp & 1;
    const int wn = warp >> 1;
    const int m0 = blockIdx.x * BM;
    const int n0 = blockIdx.y * BN;
    const int K  = K1 + K2;
    const int NCH = K / BK;

    float acc[4][4][4];
#pragma unroll
    for (int a = 0; a < 4; a++)
#pragma unroll
        for (int b = 0; b < 4; b++)
#pragma unroll
            for (int c = 0; c < 4; c++) acc[a][b][c] = 0.f;

    auto fillA = [&](unsigned* As, int ch) {
        int k0 = ch * BK;
#pragma unroll
        for (int j = 0; j < 4; j++) {
            int v = tid + 256 * j;
            int r = v >> 3;
            int c4 = (v & 7) * 4;
            int gr = m0 + r;
            unsigned* d = As + r * ASTRIDE + c4;
            if (gr < M) {
                int gc = k0 + c4;
                const float* p = (gc < K1) ? A1 + (size_t)gr * K1 + gc
                                           : A2 + (size_t)gr * K2 + (gc - K1);
                cpa16(d, p);
            } else {
                uint4 z = make_uint4(0, 0, 0, 0);
                *reinterpret_cast<uint4*>(d) = z;
            }
        }
    };

    fillA(Asb[0], 0);
    fill_B(Bsb[0], W, 0, n0, tid);
    CP_COMMIT;

#pragma unroll 1
    for (int ch = 0; ch < NCH; ch++) {
        int cur = ch & 1, nxt = cur ^ 1;
        if (ch + 1 < NCH) {
            fillA(Asb[nxt], ch + 1);
            fill_B(Bsb[nxt], W, (ch + 1) * 32, n0, tid);
        }
        CP_COMMIT;
        CP_WAIT1;
        __syncthreads();
        mma_chunk(Asb[cur], Bsb[cur], acc, wm, wn, lane);
        __syncthreads();
    }

#pragma unroll
    for (int tm = 0; tm < 4; tm++) {
#pragma unroll
        for (int tn = 0; tn < 4; tn++) {
            int mr = m0 + wm * 64 + tm * 16 + (lane >> 2);
            int nc = n0 + wn * 32 + tn * 8 + 2 * (lane & 3);
            float b0 = bias[nc], b1 = bias[nc + 1];
            float v0 = acc[tm][tn][0] + b0;
            float v1 = acc[tm][tn][1] + b1;
            float v2 = acc[tm][tn][2] + b0;
            float v3 = acc[tm][tn][3] + b1;
            if (doRelu) {
                v0 = fmaxf(v0, 0.f); v1 = fmaxf(v1, 0.f);
                v2 = fmaxf(v2, 0.f); v3 = fmaxf(v3, 0.f);
            }
            // pre-round outputs to tf32 so downstream GEMMs can cp.async directly
            v0 = __uint_as_float(f2tf(v0));
            v1 = __uint_as_float(f2tf(v1));
            v2 = __uint_as_float(f2tf(v2));
            v3 = __uint_as_float(f2tf(v3));
            if (mr < M) {
                float2 o; o.x = v0; o.y = v1;
                *reinterpret_cast<float2*>(C + (size_t)mr * HH + nc) = o;
            }
            if (mr + 8 < M) {
                float2 o; o.x = v2; o.y = v3;
                *reinterpret_cast<float2*>(C + (size_t)(mr + 8) * HH + nc) = o;
            }
        }
    }
}

// ---------------- pooling ----------------
__global__ void k_pool(const float* __restrict__ h, const int* __restrict__ batch) {
    int idx = blockIdx.x * blockDim.x + threadIdx.x;
    if (idx >= NN * HH) return;
    int n = idx >> 8;
    int c = idx & 255;
    int g = ldidx(batch, g_is64, n);
    atomicAdd(&g_pool[g * HH + c], h[idx]);
    if (c == 0) atomicAdd(&g_cnt[g], 1.0f);
}

// ---------------- head ----------------
__global__ void k_head1(const float* __restrict__ hw1, const float* __restrict__ hb1) {
    __shared__ float p[HH];
    int g = blockIdx.x;
    int t = threadIdx.x;
    float cnt = fmaxf(g_cnt[g], 1.0f);
    p[t] = g_pool[g * HH + t] / cnt;
    __syncthreads();
    float s = hb1[t];
    for (int k = 0; k < HH; k++) s += p[k] * hw1[k * HH + t];
    g_t1[g * HH + t] = fmaxf(s, 0.f);
}

__global__ void k_head2(const float* __restrict__ hw2, const float* __restrict__ hb2,
                        float* __restrict__ out) {
    __shared__ float q[HH];
    int g = blockIdx.x;
    int t = threadIdx.x;
    q[t] = g_t1[g * HH + t];
    q[t + 128] = g_t1[g * HH + t + 128];
    __syncthreads();
    float s = hb2[t];
    for (int k = 0; k < HH; k++) s += q[k] * hw2[k * OUTD + t];
    out[g * OUTD + t] = s;
}

// ---------------- launcher ----------------
extern "C" void kernel_launch(void* const* d_in, const int* in_sizes, int n_in,
                              void* d_out, int out_size)
{
    const float* x    = (const float*)d_in[0];
    const float* ea   = (const float*)d_in[1];
    const float* ew1  = (const float*)d_in[2];
    const float* eb1  = (const float*)d_in[3];
    const float* ew2  = (const float*)d_in[4];
    const float* eb2  = (const float*)d_in[5];
    const float* mw1  = (const float*)d_in[6];
    const float* mb1  = (const float*)d_in[7];
    const float* mw2  = (const float*)d_in[8];
    const float* mb2  = (const float*)d_in[9];
    const float* uw1  = (const float*)d_in[10];
    const float* ub1  = (const float*)d_in[11];
    const float* uw2  = (const float*)d_in[12];
    const float* ub2  = (const float*)d_in[13];
    const float* hw1  = (const float*)d_in[14];
    const float* hb1  = (const float*)d_in[15];
    const float* hw2  = (const float*)d_in[16];
    const float* hb2  = (const float*)d_in[17];
    const int*   eidx = (const int*)d_in[18];
    const int*   bat  = (const int*)d_in[19];
    float* out = (float*)d_out;

    void *p_h, *p_h2, *p_tmp, *p_agg, *p_M1, *p_pool, *p_cnt;
    void *p_x32, *p_ea32, *p_w32;
    cudaGetSymbolAddress(&p_h,    g_h);
    cudaGetSymbolAddress(&p_h2,   g_h2);
    cudaGetSymbolAddress(&p_tmp,  g_tmp);
    cudaGetSymbolAddress(&p_agg,  g_agg);
    cudaGetSymbolAddress(&p_M1,   g_M1);
    cudaGetSymbolAddress(&p_pool, g_pool);
    cudaGetSymbolAddress(&p_cnt,  g_cnt);
    cudaGetSymbolAddress(&p_x32,  g_x32);
    cudaGetSymbolAddress(&p_ea32, g_ea32);
    cudaGetSymbolAddress(&p_w32,  g_w32);
    float* w32 = (float*)p_w32;

    // raise dynamic smem limit (idempotent; first call happens outside capture)
    cudaFuncSetAttribute(k_edge_msg,     cudaFuncAttributeMaxDynamicSharedMemorySize, SMEM_BYTES);
    cudaFuncSetAttribute(k_edge_scatter, cudaFuncAttributeMaxDynamicSharedMemorySize, SMEM_BYTES);
    cudaFuncSetAttribute(k_node,         cudaFuncAttributeMaxDynamicSharedMemorySize, SMEM_BYTES);

    k_detect<<<1, 256>>>(eidx);

    // pre-round all GEMM operands to tf32
    auto cvt = [&](const float* src, float* dst, int n) {
        int n4 = n / 4;
        k_cvt4<<<(n4 + 255) / 256, 256>>>((const float4*)src, (float4*)dst, n4);
    };
    cvt(x,   (float*)p_x32,  NN * NFD);
    cvt(ea,  (float*)p_ea32, NE * EFD);
    cvt(ew1, w32 + OFF_EW1, NFD * HH);
    cvt(ew2, w32 + OFF_EW2, HH * HH);
    cvt(mw1, w32 + OFF_MW1, NL * (2 * HH + EFD) * HH);
    cvt(mw2, w32 + OFF_MW2, NL * HH * HH);
    cvt(uw1, w32 + OFF_UW1, NL * 2 * HH * HH);
    cvt(uw2, w32 + OFF_UW2, NL * HH * HH);

    dim3 gNode((NN + BM - 1) / BM, HH / BN);   // 157 x 2
    dim3 gEdge(NE / BM, HH / BN);              // 2500 x 2

    // embedder
    k_node<<<gNode, 256, SMEM_BYTES>>>((const float*)p_x32, NFD, nullptr, 0,
                                       w32 + OFF_EW1, eb1, (float*)p_tmp, NN, 1);
    k_node<<<gNode, 256, SMEM_BYTES>>>((const float*)p_tmp, HH, nullptr, 0,
                                       w32 + OFF_EW2, eb2, (float*)p_h, NN, 0);

    float* hc = (float*)p_h;
    float* hn = (float*)p_h2;

    for (int l = 0; l < NL; l++) {
        cudaMemsetAsync(p_agg, 0, (size_t)NN * HH * sizeof(float));
        k_edge_msg<<<gEdge, 256, SMEM_BYTES>>>(hc, (const float*)p_ea32, eidx,
                                               w32 + OFF_MW1 + (size_t)l * MW1_STRIDE,
                                               mb1 + l * HH, (float*)p_M1);
        k_edge_scatter<<<gEdge, 256, SMEM_BYTES>>>((const float*)p_M1,
                                                   w32 + OFF_MW2 + (size_t)l * MW2_STRIDE,
                                                   mb2 + l * HH, eidx, (float*)p_agg);
        cvt((const float*)p_agg, (float*)p_agg, NN * HH);   // round agg in-place
        k_node<<<gNode, 256, SMEM_BYTES>>>(hc, HH, (const float*)p_agg, HH,
                                           w32 + OFF_UW1 + (size_t)l * UW1_STRIDE,
                                           ub1 + l * HH, (float*)p_tmp, NN, 1);
        k_node<<<gNode, 256, SMEM_BYTES>>>((const float*)p_tmp, HH, nullptr, 0,
                                           w32 + OFF_UW2 + (size_t)l * UW2_STRIDE,
                                           ub2 + l * HH, hn, NN, 0);
        float* t = hc; hc = hn; hn = t;
    }

    cudaMemsetAsync(p_pool, 0, (size_t)NG * HH * sizeof(float));
    cudaMemsetAsync(p_cnt,  0, (size_t)NG * sizeof(float));
    k_pool<<<(NN * HH + 255) / 256, 256>>>(hc, bat);
    k_head1<<<NG, HH>>>(hw1, hb1);
    k_head2<<<NG, OUTD>>>(hw2, hb2, out);
}

// round 5
// speedup vs baseline: 4.7014x; 1.6509x over previous
#include <cuda_runtime.h>
#include <cuda_fp16.h>
#include <cstdint>

// Problem constants
#define NN   20000
#define NE   320000
#define NFD  128
#define EFD  32
#define HH   256
#define OUTD 128
#define NL   4
#define NG   64

// GEMM tiling (fp16 mma.m16n8k16)
#define BM 128
#define BN 128
#define BK 32              // halves per K-chunk
#define STR 40             // smem row stride in halves (32 + 8 pad) = 80 bytes

// ---------------- scratch ----------------
__device__ __half g_h   [NN * HH];
__device__ __half g_h2  [NN * HH];
__device__ __half g_tmp [NN * HH];
__device__ float  g_aggf[NN * HH];
__device__ __half g_aggh[NN * HH];
__device__ __half g_M1  [(size_t)NE * HH];
__device__ __half g_xh  [NN * NFD];
__device__ __half g_eah [(size_t)NE * EFD];
__device__ __half g_wh  [1703936];
__device__ float  g_pool[NG * HH];
__device__ float  g_cnt [NG];
__device__ float  g_t1  [NG * HH];
__device__ int    g_is64;

// weight offsets inside g_wh (transposed [N][K] layouts)
#define OFF_EW1 0
#define OFF_EW2 32768
#define OFF_MW1 98304
#define MW1_STRIDE 139264
#define OFF_MW2 655360
#define MW2_STRIDE 65536
#define OFF_UW1 917504
#define UW1_STRIDE 131072
#define OFF_UW2 1441792
#define UW2_STRIDE 65536

// ---------------- helpers ----------------
__device__ __forceinline__ void cpa16(uint32_t dst, const void* src) {
    asm volatile("cp.async.ca.shared.global [%0], [%1], 16;" :: "r"(dst), "l"(src));
}
__device__ __forceinline__ void cpa16cg(uint32_t dst, const void* src) {
    asm volatile("cp.async.cg.shared.global [%0], [%1], 16;" :: "r"(dst), "l"(src));
}
#define CP_COMMIT asm volatile("cp.async.commit_group;")
#define CP_WAIT1  asm volatile("cp.async.wait_group 1;")

__device__ __forceinline__ int ldidx(const int* w, int is64, long i) {
    return is64 ? w[2 * i] : w[(size_t)i];
}

__global__ void k_detect(const int* __restrict__ w) {
    __shared__ int nz;
    if (threadIdx.x == 0) nz = 0;
    __syncthreads();
    int local = 0;
    for (int i = 1 + 2 * threadIdx.x; i < 2 * NE; i += 2 * 256) local |= w[i];
    if (local) atomicOr(&nz, 1);
    __syncthreads();
    if (threadIdx.x == 0) g_is64 = (nz == 0) ? 1 : 0;
}

// float -> half conversion (2 per thread)
__global__ void k_f2h(const float2* __restrict__ in, __half2* __restrict__ out, int n2) {
    int i = blockIdx.x * blockDim.x + threadIdx.x;
    if (i < n2) {
        float2 v = in[i];
        out[i] = __floats2half2_rn(v.x, v.y);
    }
}

// W[K][N] fp32 -> Wt[N][K] fp16
__global__ void k_wt(const float* __restrict__ W, __half* __restrict__ Wt, int K, int N) {
    int i = blockIdx.x * blockDim.x + threadIdx.x;
    if (i < K * N) {
        int k = i / N, n = i - k * N;
        Wt[(size_t)n * K + k] = __float2half_rn(W[i]);
    }
}

// fp16 m16n8k16 MMA, fp32 accumulate
__device__ __forceinline__ void mma16(float* c, const unsigned* a, const unsigned* b) {
    asm volatile(
        "mma.sync.aligned.m16n8k16.row.col.f32.f16.f16.f32 "
        "{%0,%1,%2,%3},{%4,%5,%6,%7},{%8,%9},{%0,%1,%2,%3};"
        : "+f"(c[0]), "+f"(c[1]), "+f"(c[2]), "+f"(c[3])
        : "r"(a[0]), "r"(a[1]), "r"(a[2]), "r"(a[3]), "r"(b[0]), "r"(b[1]));
}

// One BK=32 chunk over the 64x32 warp tile (4x4 mma tiles, 2 k16 steps)
// As: [BM][STR] half row-major(m,k).  Bs: [BN][STR] half (n,k) — k contiguous.
__device__ __forceinline__ void mma_chunk(
    const __half* __restrict__ As, const __half* __restrict__ Bs,
    float acc[4][4][4], int wm, int wn, int lane)
{
    const int g = lane >> 2;        // 0..7
    const int c = lane & 3;         // 0..3
#pragma unroll
    for (int s = 0; s < 2; s++) {
        unsigned afr[4][4];
#pragma unroll
        for (int tm = 0; tm < 4; tm++) {
            int base = (wm * 64 + tm * 16 + g) * STR + s * 16 + 2 * c;
            afr[tm][0] = *(const unsigned*)&As[base];
            afr[tm][1] = *(const unsigned*)&As[base + 8 * STR];
            afr[tm][2] = *(const unsigned*)&As[base + 8];
            afr[tm][3] = *(const unsigned*)&As[base + 8 * STR + 8];
        }
        unsigned bfr[4][2];
#pragma unroll
        for (int tn = 0; tn < 4; tn++) {
            int nb = (wn * 32 + tn * 8 + g) * STR + s * 16 + 2 * c;
            bfr[tn][0] = *(const unsigned*)&Bs[nb];
            bfr[tn][1] = *(const unsigned*)&Bs[nb + 8];
        }
#pragma unroll
        for (int tm = 0; tm < 4; tm++)
#pragma unroll
            for (int tn = 0; tn < 4; tn++)
                mma16(acc[tm][tn], afr[tm], bfr[tn]);
    }
}

// Fill B tile: Bs[n][k] <- Wt[(n0+n)*Kstride + ch*32 + k], 512 16B chunks
__device__ __forceinline__ void fill_B(uint32_t bs, const __half* __restrict__ Wt,
                                       int Kstride, int ch, int n0, int tid) {
#pragma unroll
    for (int j = 0; j < 2; j++) {
        int v = tid + 256 * j;
        int r = v >> 2, c8 = v & 3;
        cpa16(bs + r * (STR * 2) + c8 * 16,
              Wt + (size_t)(n0 + r) * Kstride + ch * BK + c8 * 8);
    }
}

#define ACC_INIT \
    float acc[4][4][4]; \
    _Pragma("unroll") for (int a_ = 0; a_ < 4; a_++) \
    _Pragma("unroll") for (int b_ = 0; b_ < 4; b_++) \
    _Pragma("unroll") for (int c_ = 0; c_ < 4; c_++) acc[a_][b_][c_] = 0.f;

// ---------------- edge message GEMM1 (fused gather) ----------------
// M1[E,256] = relu( [h[dst] | h[src] | edge_attr][E,544] @ W1 + b1 )  (fp16 out)
__global__ void __launch_bounds__(256, 2)
k_edge_msg(const __half* __restrict__ h, const __half* __restrict__ ea,
           const int* __restrict__ eidx, const __half* __restrict__ Wt,
           const float* __restrict__ bias, __half* __restrict__ out)
{
    __shared__ __align__(16) __half As[2][BM * STR];
    __shared__ __align__(16) __half Bs[2][BN * STR];
    __shared__ int sDst[BM], sSrc[BM];
    __shared__ float sBias[BN];

    const int tid = threadIdx.x, lane = tid & 31, warp = tid >> 5;
    const int wm = warp & 1, wn = warp >> 1;
    const int m0 = blockIdx.x * BM;
    const int n0 = blockIdx.y * BN;
    const int is64 = g_is64;

    if (tid < BM) {
        sSrc[tid] = ldidx(eidx, is64, (long)m0 + tid);
        sDst[tid] = ldidx(eidx, is64, (long)NE + m0 + tid);
        sBias[tid] = bias[n0 + tid];
    }
    __syncthreads();

    uint32_t asb[2] = { (uint32_t)__cvta_generic_to_shared(As[0]),
                        (uint32_t)__cvta_generic_to_shared(As[1]) };
    uint32_t bsb[2] = { (uint32_t)__cvta_generic_to_shared(Bs[0]),
                        (uint32_t)__cvta_generic_to_shared(Bs[1]) };

    ACC_INIT;

    auto fillA = [&](uint32_t as, int ch) {
#pragma unroll
        for (int j = 0; j < 2; j++) {
            int v = tid + 256 * j;
            int r = v >> 2, c8 = v & 3;
            const __half* p;
            if (ch < 8)       p = h  + (size_t)sDst[r] * HH + ch * BK + c8 * 8;
            else if (ch < 16) p = h  + (size_t)sSrc[r] * HH + (ch - 8) * BK + c8 * 8;
            else              p = ea + (size_t)(m0 + r) * EFD + c8 * 8;
            cpa16(as + r * (STR * 2) + c8 * 16, p);
        }
    };

    fillA(asb[0], 0);
    fill_B(bsb[0], Wt, 544, 0, n0, tid);
    CP_COMMIT;

    const int NCH = 17;
#pragma unroll 1
    for (int ch = 0; ch < NCH; ch++) {
        int cur = ch & 1, nxt = cur ^ 1;
        if (ch + 1 < NCH) {
            fillA(asb[nxt], ch + 1);
            fill_B(bsb[nxt], Wt, 544, ch + 1, n0, tid);
        }
        CP_COMMIT;
        CP_WAIT1;
        __syncthreads();
        mma_chunk(As[cur], Bs[cur], acc, wm, wn, lane);
        __syncthreads();
    }

#pragma unroll
    for (int tm = 0; tm < 4; tm++) {
#pragma unroll
        for (int tn = 0; tn < 4; tn++) {
            int mr = m0 + wm * 64 + tm * 16 + (lane >> 2);
            int ncl = wn * 32 + tn * 8 + 2 * (lane & 3);
            float b0 = sBias[ncl], b1 = sBias[ncl + 1];
            __half2 o0 = __floats2half2_rn(fmaxf(acc[tm][tn][0] + b0, 0.f),
                                           fmaxf(acc[tm][tn][1] + b1, 0.f));
            __half2 o1 = __floats2half2_rn(fmaxf(acc[tm][tn][2] + b0, 0.f),
                                           fmaxf(acc[tm][tn][3] + b1, 0.f));
            *reinterpret_cast<__half2*>(out + (size_t)mr * HH + n0 + ncl) = o0;
            *reinterpret_cast<__half2*>(out + (size_t)(mr + 8) * HH + n0 + ncl) = o1;
        }
    }
}

// ---------------- edge GEMM2 + fused scatter-add ----------------
__global__ void __launch_bounds__(256, 2)
k_edge_scatter(const __half* __restrict__ M1, const __half* __restrict__ Wt,
               const float* __restrict__ bias, const int* __restrict__ eidx,
               float* __restrict__ agg)
{
    __shared__ __align__(16) __half As[2][BM * STR];
    __shared__ __align__(16) __half Bs[2][BN * STR];
    __shared__ int sDst[BM];
    __shared__ float sBias[BN];

    const int tid = threadIdx.x, lane = tid & 31, warp = tid >> 5;
    const int wm = warp & 1, wn = warp >> 1;
    const int m0 = blockIdx.x * BM;
    const int n0 = blockIdx.y * BN;
    const int is64 = g_is64;

    if (tid < BM) {
        sDst[tid] = ldidx(eidx, is64, (long)NE + m0 + tid);
        sBias[tid] = bias[n0 + tid];
    }
    __syncthreads();

    uint32_t asb[2] = { (uint32_t)__cvta_generic_to_shared(As[0]),
                        (uint32_t)__cvta_generic_to_shared(As[1]) };
    uint32_t bsb[2] = { (uint32_t)__cvta_generic_to_shared(Bs[0]),
                        (uint32_t)__cvta_generic_to_shared(Bs[1]) };

    ACC_INIT;

    auto fillA = [&](uint32_t as, int ch) {
#pragma unroll
        for (int j = 0; j < 2; j++) {
            int v = tid + 256 * j;
            int r = v >> 2, c8 = v & 3;
            cpa16cg(as + r * (STR * 2) + c8 * 16,
                    M1 + (size_t)(m0 + r) * HH + ch * BK + c8 * 8);
        }
    };

    fillA(asb[0], 0);
    fill_B(bsb[0], Wt, HH, 0, n0, tid);
    CP_COMMIT;

    const int NCH = 8;
#pragma unroll 1
    for (int ch = 0; ch < NCH; ch++) {
        int cur = ch & 1, nxt = cur ^ 1;
        if (ch + 1 < NCH) {
            fillA(asb[nxt], ch + 1);
            fill_B(bsb[nxt], Wt, HH, ch + 1, n0, tid);
        }
        CP_COMMIT;
        CP_WAIT1;
        __syncthreads();
        mma_chunk(As[cur], Bs[cur], acc, wm, wn, lane);
        __syncthreads();
    }

#pragma unroll
    for (int tm = 0; tm < 4; tm++) {
        int rl0 = wm * 64 + tm * 16 + (lane >> 2);
        int d0 = sDst[rl0];
        int d1 = sDst[rl0 + 8];
#pragma unroll
        for (int tn = 0; tn < 4; tn++) {
            int ncl = wn * 32 + tn * 8 + 2 * (lane & 3);
            float b0 = sBias[ncl], b1 = sBias[ncl + 1];
            atomicAdd(agg + (size_t)d0 * HH + n0 + ncl,     acc[tm][tn][0] + b0);
            atomicAdd(agg + (size_t)d0 * HH + n0 + ncl + 1, acc[tm][tn][1] + b1);
            atomicAdd(agg + (size_t)d1 * HH + n0 + ncl,     acc[tm][tn][2] + b0);
            atomicAdd(agg + (size_t)d1 * HH + n0 + ncl + 1, acc[tm][tn][3] + b1);
        }
    }
}

// ---------------- node-level GEMM (concat A1|A2) ----------------
__global__ void __launch_bounds__(256, 2)
k_node(const __half* __restrict__ A1, int K1,
       const __half* __restrict__ A2, int K2,
       const __half* __restrict__ Wt, const float* __restrict__ bias,
       __half* __restrict__ C, int M, int doRelu)
{
    __shared__ __align__(16) __half As[2][BM * STR];
    __shared__ __align__(16) __half Bs[2][BN * STR];
    __shared__ float sBias[BN];

    const int tid = threadIdx.x, lane = tid & 31, warp = tid >> 5;
    const int wm = warp & 1, wn = warp >> 1;
    const int m0 = blockIdx.x * BM;
    const int n0 = blockIdx.y * BN;
    const int K = K1 + K2;
    const int NCH = K / BK;

    if (tid < BM) sBias[tid] = bias[n0 + tid];
    __syncthreads();

    uint32_t asb[2] = { (uint32_t)__cvta_generic_to_shared(As[0]),
                        (uint32_t)__cvta_generic_to_shared(As[1]) };
    uint32_t bsb[2] = { (uint32_t)__cvta_generic_to_shared(Bs[0]),
                        (uint32_t)__cvta_generic_to_shared(Bs[1]) };

    ACC_INIT;

    auto fillA = [&](uint32_t as, int ch) {
        int k0 = ch * BK;
#pragma unroll
        for (int j = 0; j < 2; j++) {
            int v = tid + 256 * j;
            int r = v >> 2, c8 = v & 3;
            int gr = m0 + r;
            if (gr >= M) gr = M - 1;       // clamp; rows >= M never stored
            int gc = k0 + c8 * 8;
            const __half* p = (gc < K1) ? A1 + (size_t)gr * K1 + gc
                                        : A2 + (size_t)gr * K2 + (gc - K1);
            cpa16(as + r * (STR * 2) + c8 * 16, p);
        }
    };

    fillA(asb[0], 0);
    fill_B(bsb[0], Wt, K, 0, n0, tid);
    CP_COMMIT;

#pragma unroll 1
    for (int ch = 0; ch < NCH; ch++) {
        int cur = ch & 1, nxt = cur ^ 1;
        if (ch + 1 < NCH) {
            fillA(asb[nxt], ch + 1);
            fill_B(bsb[nxt], Wt, K, ch + 1, n0, tid);
        }
        CP_COMMIT;
        CP_WAIT1;
        __syncthreads();
        mma_chunk(As[cur], Bs[cur], acc, wm, wn, lane);
        __syncthreads();
    }

#pragma unroll
    for (int tm = 0; tm < 4; tm++) {
#pragma unroll
        for (int tn = 0; tn < 4; tn++) {
            int mr = m0 + wm * 64 + tm * 16 + (lane >> 2);
            int ncl = wn * 32 + tn * 8 + 2 * (lane & 3);
            float b0 = sBias[ncl], b1 = sBias[ncl + 1];
            float v0 = acc[tm][tn][0] + b0;
            float v1 = acc[tm][tn][1] + b1;
            float v2 = acc[tm][tn][2] + b0;
            float v3 = acc[tm][tn][3] + b1;
            if (doRelu) {
                v0 = fmaxf(v0, 0.f); v1 = fmaxf(v1, 0.f);
                v2 = fmaxf(v2, 0.f); v3 = fmaxf(v3, 0.f);
            }
            if (mr < M)
                *reinterpret_cast<__half2*>(C + (size_t)mr * HH + n0 + ncl) =
                    __floats2half2_rn(v0, v1);
            if (mr + 8 < M)
                *reinterpret_cast<__half2*>(C + (size_t)(mr + 8) * HH + n0 + ncl) =
                    __floats2half2_rn(v2, v3);
        }
    }
}

// ---------------- pooling ----------------
__global__ void k_pool(const __half* __restrict__ h, const int* __restrict__ batch) {
    int idx = blockIdx.x * blockDim.x + threadIdx.x;
    if (idx >= NN * HH) return;
    int n = idx >> 8;
    int c = idx & 255;
    int g = ldidx(batch, g_is64, n);
    atomicAdd(&g_pool[g * HH + c], __half2float(h[idx]));
    if (c == 0) atomicAdd(&g_cnt[g], 1.0f);
}

// ---------------- head (fp32 scalar, tiny) ----------------
__global__ void k_head1(const float* __restrict__ hw1, const float* __restrict__ hb1) {
    __shared__ float p[HH];
    int g = blockIdx.x;
    int t = threadIdx.x;
    float cnt = fmaxf(g_cnt[g], 1.0f);
    p[t] = g_pool[g * HH + t] / cnt;
    __syncthreads();
    float s = hb1[t];
    for (int k = 0; k < HH; k++) s += p[k] * hw1[k * HH + t];
    g_t1[g * HH + t] = fmaxf(s, 0.f);
}

__global__ void k_head2(const float* __restrict__ hw2, const float* __restrict__ hb2,
                        float* __restrict__ out) {
    __shared__ float q[HH];
    int g = blockIdx.x;
    int t = threadIdx.x;
    q[t] = g_t1[g * HH + t];
    q[t + 128] = g_t1[g * HH + t + 128];
    __syncthreads();
    float s = hb2[t];
    for (int k = 0; k < HH; k++) s += q[k] * hw2[k * OUTD + t];
    out[g * OUTD + t] = s;
}

// ---------------- launcher ----------------
extern "C" void kernel_launch(void* const* d_in, const int* in_sizes, int n_in,
                              void* d_out, int out_size)
{
    const float* x    = (const float*)d_in[0];
    const float* ea   = (const float*)d_in[1];
    const float* ew1  = (const float*)d_in[2];
    const float* eb1  = (const float*)d_in[3];
    const float* ew2  = (const float*)d_in[4];
    const float* eb2  = (const float*)d_in[5];
    const float* mw1  = (const float*)d_in[6];
    const float* mb1  = (const float*)d_in[7];
    const float* mw2  = (const float*)d_in[8];
    const float* mb2  = (const float*)d_in[9];
    const float* uw1  = (const float*)d_in[10];
    const float* ub1  = (const float*)d_in[11];
    const float* uw2  = (const float*)d_in[12];
    const float* ub2  = (const float*)d_in[13];
    const float* hw1  = (const float*)d_in[14];
    const float* hb1  = (const float*)d_in[15];
    const float* hw2  = (const float*)d_in[16];
    const float* hb2  = (const float*)d_in[17];
    const int*   eidx = (const int*)d_in[18];
    const int*   bat  = (const int*)d_in[19];
    float* out = (float*)d_out;

    void *p_h, *p_h2, *p_tmp, *p_aggf, *p_aggh, *p_M1, *p_pool, *p_cnt;
    void *p_xh, *p_eah, *p_wh;
    cudaGetSymbolAddress(&p_h,    g_h);
    cudaGetSymbolAddress(&p_h2,   g_h2);
    cudaGetSymbolAddress(&p_tmp,  g_tmp);
    cudaGetSymbolAddress(&p_aggf, g_aggf);
    cudaGetSymbolAddress(&p_aggh, g_aggh);
    cudaGetSymbolAddress(&p_M1,   g_M1);
    cudaGetSymbolAddress(&p_pool, g_pool);
    cudaGetSymbolAddress(&p_cnt,  g_cnt);
    cudaGetSymbolAddress(&p_xh,   g_xh);
    cudaGetSymbolAddress(&p_eah,  g_eah);
    cudaGetSymbolAddress(&p_wh,   g_wh);
    __half* wh = (__half*)p_wh;

    k_detect<<<1, 256>>>(eidx);

    auto f2h = [&](const float* src, __half* dst, size_t n) {
        int n2 = (int)(n / 2);
        k_f2h<<<(n2 + 255) / 256, 256>>>((const float2*)src, (__half2*)dst, n2);
    };
    auto wt = [&](const float* W, __half* Wt, int K, int Nn) {
        int n = K * Nn;
        k_wt<<<(n + 255) / 256, 256>>>(W, Wt, K, Nn);
    };
    f2h(x,  (__half*)p_xh,  (size_t)NN * NFD);
    f2h(ea, (__half*)p_eah, (size_t)NE * EFD);
    wt(ew1, wh + OFF_EW1, NFD, HH);
    wt(ew2, wh + OFF_EW2, HH, HH);
    for (int l = 0; l < NL; l++) {
        wt(mw1 + (size_t)l * MW1_STRIDE, wh + OFF_MW1 + (size_t)l * MW1_STRIDE, 2 * HH + EFD, HH);
        wt(mw2 + (size_t)l * MW2_STRIDE, wh + OFF_MW2 + (size_t)l * MW2_STRIDE, HH, HH);
        wt(uw1 + (size_t)l * UW1_STRIDE, wh + OFF_UW1 + (size_t)l * UW1_STRIDE, 2 * HH, HH);
        wt(uw2 + (size_t)l * UW2_STRIDE, wh + OFF_UW2 + (size_t)l * UW2_STRIDE, HH, HH);
    }

    dim3 gNode((NN + BM - 1) / BM, HH / BN);   // 157 x 2
    dim3 gEdge(NE / BM, HH / BN);              // 2500 x 2

    // embedder
    k_node<<<gNode, 256>>>((const __half*)p_xh, NFD, nullptr, 0,
                           wh + OFF_EW1, eb1, (__half*)p_tmp, NN, 1);
    k_node<<<gNode, 256>>>((const __half*)p_tmp, HH, nullptr, 0,
                           wh + OFF_EW2, eb2, (__half*)p_h, NN, 0);

    __half* hc = (__half*)p_h;
    __half* hn = (__half*)p_h2;

    for (int l = 0; l < NL; l++) {
        cudaMemsetAsync(p_aggf, 0, (size_t)NN * HH * sizeof(float));
        k_edge_msg<<<gEdge, 256>>>(hc, (const __half*)p_eah, eidx,
                                   wh + OFF_MW1 + (size_t)l * MW1_STRIDE,
                                   mb1 + l * HH, (__half*)p_M1);
        k_edge_scatter<<<gEdge, 256>>>((const __half*)p_M1,
                                       wh + OFF_MW2 + (size_t)l * MW2_STRIDE,
                                       mb2 + l * HH, eidx, (float*)p_aggf);
        f2h((const float*)p_aggf, (__half*)p_aggh, (size_t)NN * HH);
        k_node<<<gNode, 256>>>(hc, HH, (const __half*)p_aggh, HH,
                               wh + OFF_UW1 + (size_t)l * UW1_STRIDE,
                               ub1 + l * HH, (__half*)p_tmp, NN, 1);
        k_node<<<gNode, 256>>>((const __half*)p_tmp, HH, nullptr, 0,
                               wh + OFF_UW2 + (size_t)l * UW2_STRIDE,
                               ub2 + l * HH, hn, NN, 0);
        __half* t = hc; hc = hn; hn = t;
    }

    cudaMemsetAsync(p_pool, 0, (size_t)NG * HH * sizeof(float));
    cudaMemsetAsync(p_cnt,  0, (size_t)NG * sizeof(float));
    k_pool<<<(NN * HH + 255) / 256, 256>>>(hc, bat);
    k_head1<<<NG, HH>>>(hw1, hb1);
    k_head2<<<NG, OUTD>>>(hw2, hb2, out);
}

// round 6
// speedup vs baseline: 6.3893x; 1.3590x over previous
#include <cuda_runtime.h>
#include <cuda_fp16.h>
#include <cstdint>

// Problem constants
#define NN   20000
#define NE   320000
#define NFD  128
#define EFD  32
#define HH   256
#define OUTD 128
#define NL   4
#define NG   64

// GEMM tiling (fp16 mma.m16n8k16)
#define BM 128
#define BN 128
#define BK 32              // halves per K-chunk
#define STR 40             // smem row stride in halves (80 bytes)

// ---------------- scratch ----------------
__device__ __half g_h    [NN * HH];
__device__ __half g_h2   [NN * HH];
__device__ __half g_tmp  [NN * HH];
__device__ __half g_T    [NN * HH];
__device__ float  g_S    [NN * HH];       // segsum(M1) fp32 accumulator
__device__ __half g_Sh   [NN * HH];       // fp16 copy of S
__device__ float  g_indeg[NN];
__device__ __half g_xh   [NN * NFD];
__device__ __half g_eah  [(size_t)NE * EFD];
__device__ __half g_wh   [1703936];
__device__ float  g_pool [NG * HH];
__device__ float  g_cnt  [NG];
__device__ float  g_t1   [NG * HH];
__device__ int    g_is64;

// weight offsets inside g_wh (transposed [N][K] layouts)
#define OFF_EW1 0
#define OFF_EW2 32768
#define OFF_MW1 98304
#define MW1_STRIDE 139264
#define OFF_MW2 655360
#define MW2_STRIDE 65536
#define OFF_UW1 917504
#define UW1_STRIDE 131072
#define OFF_UW2 1441792
#define UW2_STRIDE 65536

// ---------------- helpers ----------------
__device__ __forceinline__ void cpa16(uint32_t dst, const void* src) {
    asm volatile("cp.async.ca.shared.global [%0], [%1], 16;" :: "r"(dst), "l"(src));
}
#define CP_COMMIT asm volatile("cp.async.commit_group;")
#define CP_WAIT1  asm volatile("cp.async.wait_group 1;")

__device__ __forceinline__ int ldidx(const int* w, int is64, long i) {
    return is64 ? w[2 * i] : w[(size_t)i];
}

__global__ void k_detect(const int* __restrict__ w) {
    __shared__ int nz;
    if (threadIdx.x == 0) nz = 0;
    __syncthreads();
    int local = 0;
    for (int i = 1 + 2 * threadIdx.x; i < 2 * NE; i += 2 * 256) local |= w[i];
    if (local) atomicOr(&nz, 1);
    __syncthreads();
    if (threadIdx.x == 0) g_is64 = (nz == 0) ? 1 : 0;
}

__global__ void k_indeg(const int* __restrict__ eidx) {
    int e = blockIdx.x * blockDim.x + threadIdx.x;
    if (e < NE) {
        int d = ldidx(eidx, g_is64, (long)NE + e);
        atomicAdd(&g_indeg[d], 1.0f);
    }
}

__global__ void k_f2h(const float2* __restrict__ in, __half2* __restrict__ out, int n2) {
    int i = blockIdx.x * blockDim.x + threadIdx.x;
    if (i < n2) {
        float2 v = in[i];
        out[i] = __floats2half2_rn(v.x, v.y);
    }
}

// W[K][N] fp32 -> Wt[N][K] fp16
__global__ void k_wt(const float* __restrict__ W, __half* __restrict__ Wt, int K, int N) {
    int i = blockIdx.x * blockDim.x + threadIdx.x;
    if (i < K * N) {
        int k = i / N, n = i - k * N;
        Wt[(size_t)n * K + k] = __float2half_rn(W[i]);
    }
}

// fp16 m16n8k16 MMA, fp32 accumulate
__device__ __forceinline__ void mma16(float* c, const unsigned* a, const unsigned* b) {
    asm volatile(
        "mma.sync.aligned.m16n8k16.row.col.f32.f16.f16.f32 "
        "{%0,%1,%2,%3},{%4,%5,%6,%7},{%8,%9},{%0,%1,%2,%3};"
        : "+f"(c[0]), "+f"(c[1]), "+f"(c[2]), "+f"(c[3])
        : "r"(a[0]), "r"(a[1]), "r"(a[2]), "r"(a[3]), "r"(b[0]), "r"(b[1]));
}

__device__ __forceinline__ void ldm4(unsigned* r, uint32_t addr) {
    asm volatile("ldmatrix.sync.aligned.m8n8.x4.shared.b16 {%0,%1,%2,%3}, [%4];"
        : "=r"(r[0]), "=r"(r[1]), "=r"(r[2]), "=r"(r[3]) : "r"(addr));
}

// One BK=32 chunk over the 64x32 warp tile, ldmatrix fragment loads.
// As: [BM][STR] (m,k).  Bs: [BN][STR] (n,k), k contiguous.
__device__ __forceinline__ void mma_chunk(
    uint32_t As, uint32_t Bs, float acc[4][4][4], int wm, int wn, int lane)
{
    const int i8 = lane & 7, q = lane >> 3;
    // A matrices: q0=(m-lo,k-lo) q1=(m-hi,k-lo) q2=(m-lo,k-hi) q3=(m-hi,k-hi)
    const int aRow = (q & 1) * 8 + i8;
    const int aCol = (q >> 1) * 8;
    // B matrices: q0=(n-lo,k-lo) q1=(n-lo,k-hi) q2=(n-hi,k-lo) q3=(n-hi,k-hi)
    const int bRow = (q >> 1) * 8 + i8;
    const int bCol = (q & 1) * 8;
#pragma unroll
    for (int s = 0; s < 2; s++) {
        unsigned afr[4][4];
#pragma unroll
        for (int tm = 0; tm < 4; tm++)
            ldm4(afr[tm], As + ((wm * 64 + tm * 16 + aRow) * STR + s * 16 + aCol) * 2);
        unsigned btmp[2][4];
#pragma unroll
        for (int p = 0; p < 2; p++)
            ldm4(btmp[p], Bs + ((wn * 32 + p * 16 + bRow) * STR + s * 16 + bCol) * 2);
#pragma unroll
        for (int tm = 0; tm < 4; tm++) {
#pragma unroll
            for (int p = 0; p < 2; p++) {
                unsigned b0[2] = { btmp[p][0], btmp[p][1] };
                unsigned b1[2] = { btmp[p][2], btmp[p][3] };
                mma16(acc[tm][2 * p],     afr[tm], b0);
                mma16(acc[tm][2 * p + 1], afr[tm], b1);
            }
        }
    }
}

// Fill B tile: Bs[n][k] <- Wt[(n0+n)*Kstride + ch*32 + k]
__device__ __forceinline__ void fill_B(uint32_t bs, const __half* __restrict__ Wt,
                                       int Kstride, int ch, int n0, int tid) {
#pragma unroll
    for (int j = 0; j < 2; j++) {
        int v = tid + 256 * j;
        int r = v >> 2, c8 = v & 3;
        cpa16(bs + r * (STR * 2) + c8 * 16,
              Wt + (size_t)(n0 + r) * Kstride + ch * BK + c8 * 8);
    }
}

#define ACC_INIT \
    float acc[4][4][4]; \
    _Pragma("unroll") for (int a_ = 0; a_ < 4; a_++) \
    _Pragma("unroll") for (int b_ = 0; b_ < 4; b_++) \
    _Pragma("unroll") for (int c_ = 0; c_ < 4; c_++) acc[a_][b_][c_] = 0.f;

// ---------------- edge message GEMM1 + fused scatter of M1 into S ----------------
// S[dst[e]] += relu( [h[dst]|h[src]|edge_attr][E,544] @ W1 + b1 )
__global__ void __launch_bounds__(256, 2)
k_edge_msg(const __half* __restrict__ h, const __half* __restrict__ ea,
           const int* __restrict__ eidx, const __half* __restrict__ Wt,
           const float* __restrict__ bias, float* __restrict__ S)
{
    __shared__ __align__(16) __half As[2][BM * STR];
    __shared__ __align__(16) __half Bs[2][BN * STR];
    __shared__ int sDst[BM], sSrc[BM];
    __shared__ float sBias[BN];

    const int tid = threadIdx.x, lane = tid & 31, warp = tid >> 5;
    const int wm = warp & 1, wn = warp >> 1;
    const int m0 = blockIdx.x * BM;
    const int n0 = blockIdx.y * BN;
    const int is64 = g_is64;

    if (tid < BM) {
        sSrc[tid] = ldidx(eidx, is64, (long)m0 + tid);
        sDst[tid] = ldidx(eidx, is64, (long)NE + m0 + tid);
        sBias[tid] = bias[n0 + tid];
    }
    __syncthreads();

    uint32_t asb[2] = { (uint32_t)__cvta_generic_to_shared(As[0]),
                        (uint32_t)__cvta_generic_to_shared(As[1]) };
    uint32_t bsb[2] = { (uint32_t)__cvta_generic_to_shared(Bs[0]),
                        (uint32_t)__cvta_generic_to_shared(Bs[1]) };

    ACC_INIT;

    auto fillA = [&](uint32_t as, int ch) {
#pragma unroll
        for (int j = 0; j < 2; j++) {
            int v = tid + 256 * j;
            int r = v >> 2, c8 = v & 3;
            const __half* p;
            if (ch < 8)       p = h  + (size_t)sDst[r] * HH + ch * BK + c8 * 8;
            else if (ch < 16) p = h  + (size_t)sSrc[r] * HH + (ch - 8) * BK + c8 * 8;
            else              p = ea + (size_t)(m0 + r) * EFD + c8 * 8;
            cpa16(as + r * (STR * 2) + c8 * 16, p);
        }
    };

    fillA(asb[0], 0);
    fill_B(bsb[0], Wt, 544, 0, n0, tid);
    CP_COMMIT;

    const int NCH = 17;
#pragma unroll 1
    for (int ch = 0; ch < NCH; ch++) {
        int cur = ch & 1, nxt = cur ^ 1;
        if (ch + 1 < NCH) {
            fillA(asb[nxt], ch + 1);
            fill_B(bsb[nxt], Wt, 544, ch + 1, n0, tid);
        }
        CP_COMMIT;
        CP_WAIT1;
        __syncthreads();
        mma_chunk(asb[cur], bsb[cur], acc, wm, wn, lane);
        __syncthreads();
    }

    // epilogue: bias + relu, scatter-add message rows into S[dst]
#pragma unroll
    for (int tm = 0; tm < 4; tm++) {
        int rl0 = wm * 64 + tm * 16 + (lane >> 2);
        int d0 = sDst[rl0];
        int d1 = sDst[rl0 + 8];
#pragma unroll
        for (int tn = 0; tn < 4; tn++) {
            int ncl = wn * 32 + tn * 8 + 2 * (lane & 3);
            float b0 = sBias[ncl], b1 = sBias[ncl + 1];
            atomicAdd(S + (size_t)d0 * HH + n0 + ncl,     fmaxf(acc[tm][tn][0] + b0, 0.f));
            atomicAdd(S + (size_t)d0 * HH + n0 + ncl + 1, fmaxf(acc[tm][tn][1] + b1, 0.f));
            atomicAdd(S + (size_t)d1 * HH + n0 + ncl,     fmaxf(acc[tm][tn][2] + b0, 0.f));
            atomicAdd(S + (size_t)d1 * HH + n0 + ncl + 1, fmaxf(acc[tm][tn][3] + b1, 0.f));
        }
    }
}

// ---------------- node-level GEMM (concat A1|A2, optional per-row bias scale) ----
// C = act( [A1|A2] @ Wt^T + bias * (rowScale ? rowScale[row] : 1) )
__global__ void __launch_bounds__(256, 2)
k_node(const __half* __restrict__ A1, int K1,
       const __half* __restrict__ A2, int K2,
       const __half* __restrict__ Wt, const float* __restrict__ bias,
       __half* __restrict__ C, int M, int doRelu,
       const float* __restrict__ rowScale)
{
    __shared__ __align__(16) __half As[2][BM * STR];
    __shared__ __align__(16) __half Bs[2][BN * STR];
    __shared__ float sBias[BN];

    const int tid = threadIdx.x, lane = tid & 31, warp = tid >> 5;
    const int wm = warp & 1, wn = warp >> 1;
    const int m0 = blockIdx.x * BM;
    const int n0 = blockIdx.y * BN;
    const int K = K1 + K2;
    const int NCH = K / BK;

    if (tid < BM) sBias[tid] = bias[n0 + tid];
    __syncthreads();

    uint32_t asb[2] = { (uint32_t)__cvta_generic_to_shared(As[0]),
                        (uint32_t)__cvta_generic_to_shared(As[1]) };
    uint32_t bsb[2] = { (uint32_t)__cvta_generic_to_shared(Bs[0]),
                        (uint32_t)__cvta_generic_to_shared(Bs[1]) };

    ACC_INIT;

    auto fillA = [&](uint32_t as, int ch) {
        int k0 = ch * BK;
#pragma unroll
        for (int j = 0; j < 2; j++) {
            int v = tid + 256 * j;
            int r = v >> 2, c8 = v & 3;
            int gr = m0 + r;
            if (gr >= M) gr = M - 1;       // clamp; rows >= M never stored
            int gc = k0 + c8 * 8;
            const __half* p = (gc < K1) ? A1 + (size_t)gr * K1 + gc
                                        : A2 + (size_t)gr * K2 + (gc - K1);
            cpa16(as + r * (STR * 2) + c8 * 16, p);
        }
    };

    fillA(asb[0], 0);
    fill_B(bsb[0], Wt, K, 0, n0, tid);
    CP_COMMIT;

#pragma unroll 1
    for (int ch = 0; ch < NCH; ch++) {
        int cur = ch & 1, nxt = cur ^ 1;
        if (ch + 1 < NCH) {
            fillA(asb[nxt], ch + 1);
            fill_B(bsb[nxt], Wt, K, ch + 1, n0, tid);
        }
        CP_COMMIT;
        CP_WAIT1;
        __syncthreads();
        mma_chunk(asb[cur], bsb[cur], acc, wm, wn, lane);
        __syncthreads();
    }

#pragma unroll
    for (int tm = 0; tm < 4; tm++) {
        int mr = m0 + wm * 64 + tm * 16 + (lane >> 2);
        float sc0 = 1.f, sc1 = 1.f;
        if (rowScale) {
            sc0 = rowScale[mr < M ? mr : M - 1];
            sc1 = rowScale[(mr + 8) < M ? (mr + 8) : M - 1];
        }
#pragma unroll
        for (int tn = 0; tn < 4; tn++) {
            int ncl = wn * 32 + tn * 8 + 2 * (lane & 3);
            float b0 = sBias[ncl], b1 = sBias[ncl + 1];
            float v0 = acc[tm][tn][0] + b0 * sc0;
            float v1 = acc[tm][tn][1] + b1 * sc0;
            float v2 = acc[tm][tn][2] + b0 * sc1;
            float v3 = acc[tm][tn][3] + b1 * sc1;
            if (doRelu) {
                v0 = fmaxf(v0, 0.f); v1 = fmaxf(v1, 0.f);
                v2 = fmaxf(v2, 0.f); v3 = fmaxf(v3, 0.f);
            }
            if (mr < M)
                *reinterpret_cast<__half2*>(C + (size_t)mr * HH + n0 + ncl) =
                    __floats2half2_rn(v0, v1);
            if (mr + 8 < M)
                *reinterpret_cast<__half2*>(C + (size_t)(mr + 8) * HH + n0 + ncl) =
                    __floats2half2_rn(v2, v3);
        }
    }
}

// ---------------- pooling ----------------
__global__ void k_pool(const __half* __restrict__ h, const int* __restrict__ batch) {
    int idx = blockIdx.x * blockDim.x + threadIdx.x;
    if (idx >= NN * HH) return;
    int n = idx >> 8;
    int c = idx & 255;
    int g = ldidx(batch, g_is64, n);
    atomicAdd(&g_pool[g * HH + c], __half2float(h[idx]));
    if (c == 0) atomicAdd(&g_cnt[g], 1.0f);
}

// ---------------- head ----------------
__global__ void k_head1(const float* __restrict__ hw1, const float* __restrict__ hb1) {
    __shared__ float p[HH];
    int g = blockIdx.x;
    int t = threadIdx.x;
    float cnt = fmaxf(g_cnt[g], 1.0f);
    p[t] = g_pool[g * HH + t] / cnt;
    __syncthreads();
    float s = hb1[t];
    for (int k = 0; k < HH; k++) s += p[k] * hw1[k * HH + t];
    g_t1[g * HH + t] = fmaxf(s, 0.f);
}

__global__ void k_head2(const float* __restrict__ hw2, const float* __restrict__ hb2,
                        float* __restrict__ out) {
    __shared__ float q[HH];
    int g = blockIdx.x;
    int t = threadIdx.x;
    q[t] = g_t1[g * HH + t];
    q[t + 128] = g_t1[g * HH + t + 128];
    __syncthreads();
    float s = hb2[t];
    for (int k = 0; k < HH; k++) s += q[k] * hw2[k * OUTD + t];
    out[g * OUTD + t] = s;
}

// ---------------- launcher ----------------
extern "C" void kernel_launch(void* const* d_in, const int* in_sizes, int n_in,
                              void* d_out, int out_size)
{
    const float* x    = (const float*)d_in[0];
    const float* ea   = (const float*)d_in[1];
    const float* ew1  = (const float*)d_in[2];
    const float* eb1  = (const float*)d_in[3];
    const float* ew2  = (const float*)d_in[4];
    const float* eb2  = (const float*)d_in[5];
    const float* mw1  = (const float*)d_in[6];
    const float* mb1  = (const float*)d_in[7];
    const float* mw2  = (const float*)d_in[8];
    const float* mb2  = (const float*)d_in[9];
    const float* uw1  = (const float*)d_in[10];
    const float* ub1  = (const float*)d_in[11];
    const float* uw2  = (const float*)d_in[12];
    const float* ub2  = (const float*)d_in[13];
    const float* hw1  = (const float*)d_in[14];
    const float* hb1  = (const float*)d_in[15];
    const float* hw2  = (const float*)d_in[16];
    const float* hb2  = (const float*)d_in[17];
    const int*   eidx = (const int*)d_in[18];
    const int*   bat  = (const int*)d_in[19];
    float* out = (float*)d_out;

    void *p_h, *p_h2, *p_tmp, *p_T, *p_S, *p_Sh, *p_indeg, *p_pool, *p_cnt;
    void *p_xh, *p_eah, *p_wh;
    cudaGetSymbolAddress(&p_h,     g_h);
    cudaGetSymbolAddress(&p_h2,    g_h2);
    cudaGetSymbolAddress(&p_tmp,   g_tmp);
    cudaGetSymbolAddress(&p_T,     g_T);
    cudaGetSymbolAddress(&p_S,     g_S);
    cudaGetSymbolAddress(&p_Sh,    g_Sh);
    cudaGetSymbolAddress(&p_indeg, g_indeg);
    cudaGetSymbolAddress(&p_pool,  g_pool);
    cudaGetSymbolAddress(&p_cnt,   g_cnt);
    cudaGetSymbolAddress(&p_xh,    g_xh);
    cudaGetSymbolAddress(&p_eah,   g_eah);
    cudaGetSymbolAddress(&p_wh,    g_wh);
    __half* wh = (__half*)p_wh;

    k_detect<<<1, 256>>>(eidx);
    cudaMemsetAsync(p_indeg, 0, NN * sizeof(float));
    k_indeg<<<(NE + 255) / 256, 256>>>(eidx);

    auto f2h = [&](const float* src, __half* dst, size_t n) {
        int n2 = (int)(n / 2);
        k_f2h<<<(n2 + 255) / 256, 256>>>((const float2*)src, (__half2*)dst, n2);
    };
    auto wt = [&](const float* W, __half* Wt, int K, int Nn) {
        int n = K * Nn;
        k_wt<<<(n + 255) / 256, 256>>>(W, Wt, K, Nn);
    };
    f2h(x,  (__half*)p_xh,  (size_t)NN * NFD);
    f2h(ea, (__half*)p_eah, (size_t)NE * EFD);
    wt(ew1, wh + OFF_EW1, NFD, HH);
    wt(ew2, wh + OFF_EW2, HH, HH);
    for (int l = 0; l < NL; l++) {
        wt(mw1 + (size_t)l * MW1_STRIDE, wh + OFF_MW1 + (size_t)l * MW1_STRIDE, 2 * HH + EFD, HH);
        wt(mw2 + (size_t)l * MW2_STRIDE, wh + OFF_MW2 + (size_t)l * MW2_STRIDE, HH, HH);
        wt(uw1 + (size_t)l * UW1_STRIDE, wh + OFF_UW1 + (size_t)l * UW1_STRIDE, 2 * HH, HH);
        wt(uw2 + (size_t)l * UW2_STRIDE, wh + OFF_UW2 + (size_t)l * UW2_STRIDE, HH, HH);
    }

    dim3 gNode((NN + BM - 1) / BM, HH / BN);   // 157 x 2
    dim3 gEdge(NE / BM, HH / BN);              // 2500 x 2

    // embedder
    k_node<<<gNode, 256>>>((const __half*)p_xh, NFD, nullptr, 0,
                           wh + OFF_EW1, eb1, (__half*)p_tmp, NN, 1, nullptr);
    k_node<<<gNode, 256>>>((const __half*)p_tmp, HH, nullptr, 0,
                           wh + OFF_EW2, eb2, (__half*)p_h, NN, 0, nullptr);

    __half* hc = (__half*)p_h;
    __half* hn = (__half*)p_h2;

    for (int l = 0; l < NL; l++) {
        cudaMemsetAsync(p_S, 0, (size_t)NN * HH * sizeof(float));
        // GEMM1 + scatter segsum(M1) into S
        k_edge_msg<<<gEdge, 256>>>(hc, (const __half*)p_eah, eidx,
                                   wh + OFF_MW1 + (size_t)l * MW1_STRIDE,
                                   mb1 + l * HH, (float*)p_S);
        f2h((const float*)p_S, (__half*)p_Sh, (size_t)NN * HH);
        // agg = S @ W2 + indeg * b2  (factored-out edge GEMM2)
        k_node<<<gNode, 256>>>((const __half*)p_Sh, HH, nullptr, 0,
                               wh + OFF_MW2 + (size_t)l * MW2_STRIDE,
                               mb2 + l * HH, (__half*)p_T, NN, 0, (const float*)p_indeg);
        // update MLP
        k_node<<<gNode, 256>>>(hc, HH, (const __half*)p_T, HH,
                               wh + OFF_UW1 + (size_t)l * UW1_STRIDE,
                               ub1 + l * HH, (__half*)p_tmp, NN, 1, nullptr);
        k_node<<<gNode, 256>>>((const __half*)p_tmp, HH, nullptr, 0,
                               wh + OFF_UW2 + (size_t)l * UW2_STRIDE,
                               ub2 + l * HH, hn, NN, 0, nullptr);
        __half* t = hc; hc = hn; hn = t;
    }

    cudaMemsetAsync(p_pool, 0, (size_t)NG * HH * sizeof(float));
    cudaMemsetAsync(p_cnt,  0, (size_t)NG * sizeof(float));
    k_pool<<<(NN * HH + 255) / 256, 256>>>(hc, bat);
    k_head1<<<NG, HH>>>(hw1, hb1);
    k_head2<<<NG, OUTD>>>(hw2, hb2, out);
}

// round 8
// speedup vs baseline: 9.8581x; 1.5429x over previous
#include <cuda_runtime.h>
#include <cuda_fp16.h>
#include <cstdint>

// Problem constants
#define NN   20000
#define NE   320000
#define NFD  128
#define EFD  32
#define HH   256
#define OUTD 128
#define NL   4
#define NG   64

// GEMM tiling (fp16 mma.m16n8k16)
#define BM 128
#define BN 128
#define BK 32
#define STR 40             // smem row stride in halves (80 bytes)

// ---------------- scratch ----------------
__device__ __half g_h    [NN * HH];
__device__ __half g_h2   [NN * HH];
__device__ __half g_tmp  [NN * HH];
__device__ __half g_Sh   [NN * HH];
__device__ float  g_PQ   [NN * 2 * HH];         // [n][0:256]=P, [256:512]=Q
__device__ float  g_R    [(size_t)NE * HH];     // ea@W1c + b1 (fp32, 328MB)
__device__ float  g_indeg[NN];
__device__ int    g_ecnt [NN];
__device__ int    g_eoff [NN + 1];
__device__ int    g_ecur [NN];
__device__ int    g_eord [NE];
__device__ __half g_xh   [NN * NFD];
__device__ __half g_eah  [(size_t)NE * EFD];
// transposed fp16 weights
__device__ __half g_wemb1[NFD * HH];
__device__ __half g_wemb2[HH * HH];
__device__ __half g_wpq  [NL][2 * HH * HH];     // [n(512)][k(256)]
__device__ __half g_w1c  [NL][HH * EFD];        // [n(256)][k(32)]
__device__ __half g_wfu  [NL][HH * 2 * HH];     // [n(256)][k(512)]
__device__ __half g_wu2  [NL][HH * HH];
__device__ float  g_w2u  [HH * HH];             // temp fp32, reused per layer
__device__ float  g_cvec [NL][HH];
__device__ float  g_pool [NG * HH];
__device__ float  g_cnt  [NG];
__device__ float  g_t1   [NG * HH];
__device__ int    g_is64;

// ---------------- helpers ----------------
__device__ __forceinline__ void cpa16(uint32_t dst, const void* src) {
    asm volatile("cp.async.ca.shared.global [%0], [%1], 16;" :: "r"(dst), "l"(src));
}
#define CP_COMMIT asm volatile("cp.async.commit_group;")
#define CP_WAIT1  asm volatile("cp.async.wait_group 1;")

__device__ __forceinline__ int ldidx(const int* w, int is64, long i) {
    return is64 ? w[2 * i] : w[(size_t)i];
}

__global__ void k_detect(const int* __restrict__ w) {
    __shared__ int nz;
    if (threadIdx.x == 0) nz = 0;
    __syncthreads();
    int local = 0;
    for (int i = 1 + 2 * threadIdx.x; i < 2 * NE; i += 2 * 256) local |= w[i];
    if (local) atomicOr(&nz, 1);
    __syncthreads();
    if (threadIdx.x == 0) g_is64 = (nz == 0) ? 1 : 0;
}

// ---------------- CSR build ----------------
__global__ void k_hist(const int* __restrict__ eidx) {
    int e = blockIdx.x * blockDim.x + threadIdx.x;
    if (e < NE) {
        int d = ldidx(eidx, g_is64, (long)NE + e);
        atomicAdd(&g_ecnt[d], 1);
    }
}

__global__ void k_scan() {     // 1 block, 1024 threads
    __shared__ int buf[1024];
    __shared__ int carry;
    int tid = threadIdx.x;
    if (tid == 0) carry = 0;
    __syncthreads();
    for (int base = 0; base < NN; base += 1024) {
        int v = (base + tid < NN) ? g_ecnt[base + tid] : 0;
        buf[tid] = v;
        __syncthreads();
        for (int s = 1; s < 1024; s <<= 1) {
            int t = (tid >= s) ? buf[tid - s] : 0;
            __syncthreads();
            buf[tid] += t;
            __syncthreads();
        }
        int excl = buf[tid] - v;
        if (base + tid < NN) {
            g_eoff[base + tid] = carry + excl;
            g_ecur[base + tid] = carry + excl;
            g_indeg[base + tid] = (float)v;
        }
        __syncthreads();
        if (tid == 1023) carry += buf[1023];
        __syncthreads();
    }
    if (tid == 0) g_eoff[NN] = carry;
}

__global__ void k_fillcsr(const int* __restrict__ eidx) {
    int e = blockIdx.x * blockDim.x + threadIdx.x;
    if (e < NE) {
        int d = ldidx(eidx, g_is64, (long)NE + e);
        int pos = atomicAdd(&g_ecur[d], 1);
        g_eord[pos] = e;
    }
}

// ---------------- conversions / weight prep ----------------
__global__ void k_f2h(const float2* __restrict__ in, __half2* __restrict__ out, int n2) {
    int i = blockIdx.x * blockDim.x + threadIdx.x;
    if (i < n2) {
        float2 v = in[i];
        out[i] = __floats2half2_rn(v.x, v.y);
    }
}

// W[K][N] fp32 -> Wt[N][K] fp16
__global__ void k_wt(const float* __restrict__ W, __half* __restrict__ Wt, int K, int N) {
    int i = blockIdx.x * blockDim.x + threadIdx.x;
    if (i < K * N) {
        int k = i / N, n = i - k * N;
        Wt[(size_t)n * K + k] = __float2half_rn(W[i]);
    }
}

// W2u[k][n] = sum_j W2[k][j] * uw1b[j][n]   (256x256x256 fp32, tiled)
__global__ void k_w2u(const float* __restrict__ W2, const float* __restrict__ uw1b,
                      float* __restrict__ out) {
    __shared__ float a[16][17], b[16][17];
    int ty = threadIdx.y, tx = threadIdx.x;
    int k = blockIdx.y * 16 + ty, n = blockIdx.x * 16 + tx;
    float s = 0.f;
    for (int j0 = 0; j0 < HH; j0 += 16) {
        a[ty][tx] = W2[k * HH + j0 + tx];
        b[ty][tx] = uw1b[(j0 + ty) * HH + n];
        __syncthreads();
#pragma unroll
        for (int j = 0; j < 16; j++) s += a[ty][j] * b[j][tx];
        __syncthreads();
    }
    out[k * HH + n] = s;
}

// pack fused update weight: Wfu[n][k] = k<256 ? uw1_top[k][n] : W2u[k-256][n]
__global__ void k_packfu(const float* __restrict__ uw1, const float* __restrict__ w2u,
                         __half* __restrict__ wfu) {
    int i = blockIdx.x * blockDim.x + threadIdx.x;
    if (i < HH * 2 * HH) {
        int n = i >> 9, k = i & 511;
        float v = (k < HH) ? uw1[k * HH + n] : w2u[(k - HH) * HH + n];
        wfu[(size_t)n * (2 * HH) + k] = __float2half_rn(v);
    }
}

// c[n] = sum_j b2[j] * uw1b[j][n]
__global__ void k_cvec(const float* __restrict__ b2, const float* __restrict__ uw1b,
                       float* __restrict__ c) {
    int n = threadIdx.x;
    float s = 0.f;
    for (int j = 0; j < HH; j++) s += b2[j] * uw1b[j * HH + n];
    c[n] = s;
}

// ---------------- fp16 tensor-core GEMM ----------------
__device__ __forceinline__ void mma16(float* c, const unsigned* a, const unsigned* b) {
    asm volatile(
        "mma.sync.aligned.m16n8k16.row.col.f32.f16.f16.f32 "
        "{%0,%1,%2,%3},{%4,%5,%6,%7},{%8,%9},{%0,%1,%2,%3};"
        : "+f"(c[0]), "+f"(c[1]), "+f"(c[2]), "+f"(c[3])
        : "r"(a[0]), "r"(a[1]), "r"(a[2]), "r"(a[3]), "r"(b[0]), "r"(b[1]));
}

__device__ __forceinline__ void ldm4(unsigned* r, uint32_t addr) {
    asm volatile("ldmatrix.sync.aligned.m8n8.x4.shared.b16 {%0,%1,%2,%3}, [%4];"
        : "=r"(r[0]), "=r"(r[1]), "=r"(r[2]), "=r"(r[3]) : "r"(addr));
}

__device__ __forceinline__ void mma_chunk(
    uint32_t As, uint32_t Bs, float acc[4][4][4], int wm, int wn, int lane)
{
    const int i8 = lane & 7, q = lane >> 3;
    const int aRow = (q & 1) * 8 + i8;
    const int aCol = (q >> 1) * 8;
    const int bRow = (q >> 1) * 8 + i8;
    const int bCol = (q & 1) * 8;
#pragma unroll
    for (int s = 0; s < 2; s++) {
        unsigned afr[4][4];
#pragma unroll
        for (int tm = 0; tm < 4; tm++)
            ldm4(afr[tm], As + ((wm * 64 + tm * 16 + aRow) * STR + s * 16 + aCol) * 2);
        unsigned btmp[2][4];
#pragma unroll
        for (int p = 0; p < 2; p++)
            ldm4(btmp[p], Bs + ((wn * 32 + p * 16 + bRow) * STR + s * 16 + bCol) * 2);
#pragma unroll
        for (int tm = 0; tm < 4; tm++) {
#pragma unroll
            for (int p = 0; p < 2; p++) {
                unsigned b0[2] = { btmp[p][0], btmp[p][1] };
                unsigned b1[2] = { btmp[p][2], btmp[p][3] };
                mma16(acc[tm][2 * p],     afr[tm], b0);
                mma16(acc[tm][2 * p + 1], afr[tm], b1);
            }
        }
    }
}

__device__ __forceinline__ void fill_B(uint32_t bs, const __half* __restrict__ Wt,
                                       int Kstride, int ch, int n0, int tid) {
#pragma unroll
    for (int j = 0; j < 2; j++) {
        int v = tid + 256 * j;
        int r = v >> 2, c8 = v & 3;
        cpa16(bs + r * (STR * 2) + c8 * 16,
              Wt + (size_t)(n0 + r) * Kstride + ch * BK + c8 * 8);
    }
}

#define ACC_INIT \
    float acc[4][4][4]; \
    _Pragma("unroll") for (int a_ = 0; a_ < 4; a_++) \
    _Pragma("unroll") for (int b_ = 0; b_ < 4; b_++) \
    _Pragma("unroll") for (int c_ = 0; c_ < 4; c_++) acc[a_][b_][c_] = 0.f;

// Generic GEMM: C = act( [A1|A2] @ Wt^T + bias + rowScale*bias2 )
// Output fp16 (Ch) or fp32 (Cf), row stride ldc.
__global__ void __launch_bounds__(256, 2)
k_node(const __half* __restrict__ A1, int K1,
       const __half* __restrict__ A2, int K2,
       const __half* __restrict__ Wt, const float* __restrict__ bias,
       const float* __restrict__ bias2, const float* __restrict__ rowScale,
       __half* __restrict__ Ch, float* __restrict__ Cf, int ldc,
       int M, int doRelu)
{
    __shared__ __align__(16) __half As[2][BM * STR];
    __shared__ __align__(16) __half Bs[2][BN * STR];
    __shared__ float sBias[BN], sBias2[BN];

    const int tid = threadIdx.x, lane = tid & 31, warp = tid >> 5;
    const int wm = warp & 1, wn = warp >> 1;
    const int m0 = blockIdx.x * BM;
    const int n0 = blockIdx.y * BN;
    const int K = K1 + K2;
    const int NCH = K / BK;

    if (tid < BM) {
        sBias[tid]  = bias  ? bias[n0 + tid]  : 0.f;
        sBias2[tid] = bias2 ? bias2[n0 + tid] : 0.f;
    }
    __syncthreads();

    uint32_t asb[2] = { (uint32_t)__cvta_generic_to_shared(As[0]),
                        (uint32_t)__cvta_generic_to_shared(As[1]) };
    uint32_t bsb[2] = { (uint32_t)__cvta_generic_to_shared(Bs[0]),
                        (uint32_t)__cvta_generic_to_shared(Bs[1]) };

    ACC_INIT;

    auto fillA = [&](uint32_t as, int ch) {
        int k0 = ch * BK;
#pragma unroll
        for (int j = 0; j < 2; j++) {
            int v = tid + 256 * j;
            int r = v >> 2, c8 = v & 3;
            int gr = m0 + r;
            if (gr >= M) gr = M - 1;
            int gc = k0 + c8 * 8;
            const __half* p = (gc < K1) ? A1 + (size_t)gr * K1 + gc
                                        : A2 + (size_t)gr * K2 + (gc - K1);
            cpa16(as + r * (STR * 2) + c8 * 16, p);
        }
    };

    fillA(asb[0], 0);
    fill_B(bsb[0], Wt, K, 0, n0, tid);
    CP_COMMIT;

#pragma unroll 1
    for (int ch = 0; ch < NCH; ch++) {
        int cur = ch & 1, nxt = cur ^ 1;
        if (ch + 1 < NCH) {
            fillA(asb[nxt], ch + 1);
            fill_B(bsb[nxt], Wt, K, ch + 1, n0, tid);
        }
        CP_COMMIT;
        CP_WAIT1;
        __syncthreads();
        mma_chunk(asb[cur], bsb[cur], acc, wm, wn, lane);
        __syncthreads();
    }

#pragma unroll
    for (int tm = 0; tm < 4; tm++) {
        int mr = m0 + wm * 64 + tm * 16 + (lane >> 2);
        float sc0 = 0.f, sc1 = 0.f;
        if (rowScale) {
            sc0 = rowScale[mr < M ? mr : M - 1];
            sc1 = rowScale[(mr + 8) < M ? (mr + 8) : M - 1];
        }
#pragma unroll
        for (int tn = 0; tn < 4; tn++) {
            int ncl = wn * 32 + tn * 8 + 2 * (lane & 3);
            float b0 = sBias[ncl], b1 = sBias[ncl + 1];
            float c0 = sBias2[ncl], c1 = sBias2[ncl + 1];
            float v0 = acc[tm][tn][0] + b0 + sc0 * c0;
            float v1 = acc[tm][tn][1] + b1 + sc0 * c1;
            float v2 = acc[tm][tn][2] + b0 + sc1 * c0;
            float v3 = acc[tm][tn][3] + b1 + sc1 * c1;
            if (doRelu) {
                v0 = fmaxf(v0, 0.f); v1 = fmaxf(v1, 0.f);
                v2 = fmaxf(v2, 0.f); v3 = fmaxf(v3, 0.f);
            }
            if (Cf) {
                if (mr < M) {
                    float2 o; o.x = v0; o.y = v1;
                    *reinterpret_cast<float2*>(Cf + (size_t)mr * ldc + n0 + ncl) = o;
                }
                if (mr + 8 < M) {
                    float2 o; o.x = v2; o.y = v3;
                    *reinterpret_cast<float2*>(Cf + (size_t)(mr + 8) * ldc + n0 + ncl) = o;
                }
            } else {
                if (mr < M)
                    *reinterpret_cast<__half2*>(Ch + (size_t)mr * ldc + n0 + ncl) =
                        __floats2half2_rn(v0, v1);
                if (mr + 8 < M)
                    *reinterpret_cast<__half2*>(Ch + (size_t)(mr + 8) * ldc + n0 + ncl) =
                        __floats2half2_rn(v2, v3);
            }
        }
    }
}

// ---------------- gather: S[n] = sum_{e in in(n)} relu(P[n]+Q[src]+R[e]) ---------
__global__ void __launch_bounds__(256)
k_gather(const float* __restrict__ PQ, const float* __restrict__ R,
         const int* __restrict__ eidx, __half* __restrict__ Sh)
{
    int n = blockIdx.x * 8 + (threadIdx.x >> 5);
    int lane = threadIdx.x & 31;
    if (n >= NN) return;
    int c0 = lane * 8;
    const int is64 = g_is64;

    float4 pa = *(const float4*)(PQ + (size_t)n * 512 + c0);
    float4 pb = *(const float4*)(PQ + (size_t)n * 512 + c0 + 4);
    float acc0 = 0.f, acc1 = 0.f, acc2 = 0.f, acc3 = 0.f;
    float acc4 = 0.f, acc5 = 0.f, acc6 = 0.f, acc7 = 0.f;

    int i = g_eoff[n], end = g_eoff[n + 1];
    for (; i + 2 <= end; i += 2) {
        int e0 = g_eord[i], e1 = g_eord[i + 1];
        int s0 = ldidx(eidx, is64, e0);
        int s1 = ldidx(eidx, is64, e1);
        float4 qa0 = *(const float4*)(PQ + (size_t)s0 * 512 + 256 + c0);
        float4 qb0 = *(const float4*)(PQ + (size_t)s0 * 512 + 256 + c0 + 4);
        float4 ra0 = *(const float4*)(R + (size_t)e0 * HH + c0);
        float4 rb0 = *(const float4*)(R + (size_t)e0 * HH + c0 + 4);
        float4 qa1 = *(const float4*)(PQ + (size_t)s1 * 512 + 256 + c0);
        float4 qb1 = *(const float4*)(PQ + (size_t)s1 * 512 + 256 + c0 + 4);
        float4 ra1 = *(const float4*)(R + (size_t)e1 * HH + c0);
        float4 rb1 = *(const float4*)(R + (size_t)e1 * HH + c0 + 4);
        acc0 += fmaxf(pa.x + qa0.x + ra0.x, 0.f) + fmaxf(pa.x + qa1.x + ra1.x, 0.f);
        acc1 += fmaxf(pa.y + qa0.y + ra0.y, 0.f) + fmaxf(pa.y + qa1.y + ra1.y, 0.f);
        acc2 += fmaxf(pa.z + qa0.z + ra0.z, 0.f) + fmaxf(pa.z + qa1.z + ra1.z, 0.f);
        acc3 += fmaxf(pa.w + qa0.w + ra0.w, 0.f) + fmaxf(pa.w + qa1.w + ra1.w, 0.f);
        acc4 += fmaxf(pb.x + qb0.x + rb0.x, 0.f) + fmaxf(pb.x + qb1.x + rb1.x, 0.f);
        acc5 += fmaxf(pb.y + qb0.y + rb0.y, 0.f) + fmaxf(pb.y + qb1.y + rb1.y, 0.f);
        acc6 += fmaxf(pb.z + qb0.z + rb0.z, 0.f) + fmaxf(pb.z + qb1.z + rb1.z, 0.f);
        acc7 += fmaxf(pb.w + qb0.w + rb0.w, 0.f) + fmaxf(pb.w + qb1.w + rb1.w, 0.f);
    }
    for (; i < end; i++) {
        int e = g_eord[i];
        int s = ldidx(eidx, is64, e);
        float4 qa = *(const float4*)(PQ + (size_t)s * 512 + 256 + c0);
        float4 qb = *(const float4*)(PQ + (size_t)s * 512 + 256 + c0 + 4);
        float4 ra = *(const float4*)(R + (size_t)e * HH + c0);
        float4 rb = *(const float4*)(R + (size_t)e * HH + c0 + 4);
        acc0 += fmaxf(pa.x + qa.x + ra.x, 0.f);
        acc1 += fmaxf(pa.y + qa.y + ra.y, 0.f);
        acc2 += fmaxf(pa.z + qa.z + ra.z, 0.f);
        acc3 += fmaxf(pa.w + qa.w + ra.w, 0.f);
        acc4 += fmaxf(pb.x + qb.x + rb.x, 0.f);
        acc5 += fmaxf(pb.y + qb.y + rb.y, 0.f);
        acc6 += fmaxf(pb.z + qb.z + rb.z, 0.f);
        acc7 += fmaxf(pb.w + qb.w + rb.w, 0.f);
    }

    __half2* o = reinterpret_cast<__half2*>(Sh + (size_t)n * HH + c0);
    o[0] = __floats2half2_rn(acc0, acc1);
    o[1] = __floats2half2_rn(acc2, acc3);
    o[2] = __floats2half2_rn(acc4, acc5);
    o[3] = __floats2half2_rn(acc6, acc7);
}

// ---------------- pooling / head ----------------
__global__ void k_pool(const __half* __restrict__ h, const int* __restrict__ batch) {
    int idx = blockIdx.x * blockDim.x + threadIdx.x;
    if (idx >= NN * HH) return;
    int n = idx >> 8;
    int c = idx & 255;
    int g = ldidx(batch, g_is64, n);
    atomicAdd(&g_pool[g * HH + c], __half2float(h[idx]));
    if (c == 0) atomicAdd(&g_cnt[g], 1.0f);
}

__global__ void k_head1(const float* __restrict__ hw1, const float* __restrict__ hb1) {
    __shared__ float p[HH];
    int g = blockIdx.x;
    int t = threadIdx.x;
    float cnt = fmaxf(g_cnt[g], 1.0f);
    p[t] = g_pool[g * HH + t] / cnt;
    __syncthreads();
    float s = hb1[t];
    for (int k = 0; k < HH; k++) s += p[k] * hw1[k * HH + t];
    g_t1[g * HH + t] = fmaxf(s, 0.f);
}

__global__ void k_head2(const float* __restrict__ hw2, const float* __restrict__ hb2,
                        float* __restrict__ out) {
    __shared__ float q[HH];
    int g = blockIdx.x;
    int t = threadIdx.x;
    q[t] = g_t1[g * HH + t];
    q[t + 128] = g_t1[g * HH + t + 128];
    __syncthreads();
    float s = hb2[t];
    for (int k = 0; k < HH; k++) s += q[k] * hw2[k * OUTD + t];
    out[g * OUTD + t] = s;
}

// ---------------- launcher ----------------
extern "C" void kernel_launch(void* const* d_in, const int* in_sizes, int n_in,
                              void* d_out, int out_size)
{
    const float* x    = (const float*)d_in[0];
    const float* ea   = (const float*)d_in[1];
    const float* ew1  = (const float*)d_in[2];
    const float* eb1  = (const float*)d_in[3];
    const float* ew2  = (const float*)d_in[4];
    const float* eb2  = (const float*)d_in[5];
    const float* mw1  = (const float*)d_in[6];
    const float* mb1  = (const float*)d_in[7];
    const float* mw2  = (const float*)d_in[8];
    const float* mb2  = (const float*)d_in[9];
    const float* uw1  = (const float*)d_in[10];
    const float* ub1  = (const float*)d_in[11];
    const float* uw2  = (const float*)d_in[12];
    const float* ub2  = (const float*)d_in[13];
    const float* hw1  = (const float*)d_in[14];
    const float* hb1  = (const float*)d_in[15];
    const float* hw2  = (const float*)d_in[16];
    const float* hb2  = (const float*)d_in[17];
    const int*   eidx = (const int*)d_in[18];
    const int*   bat  = (const int*)d_in[19];
    float* out = (float*)d_out;

    void *p_h, *p_h2, *p_tmp, *p_Sh, *p_PQ, *p_R, *p_indeg, *p_ecnt;
    void *p_xh, *p_eah, *p_wemb1, *p_wemb2, *p_wpq, *p_w1c, *p_wfu, *p_wu2;
    void *p_w2u, *p_cvec, *p_pool, *p_cnt;
    cudaGetSymbolAddress(&p_h,     g_h);
    cudaGetSymbolAddress(&p_h2,    g_h2);
    cudaGetSymbolAddress(&p_tmp,   g_tmp);
    cudaGetSymbolAddress(&p_Sh,    g_Sh);
    cudaGetSymbolAddress(&p_PQ,    g_PQ);
    cudaGetSymbolAddress(&p_R,     g_R);
    cudaGetSymbolAddress(&p_indeg, g_indeg);
    cudaGetSymbolAddress(&p_ecnt,  g_ecnt);
    cudaGetSymbolAddress(&p_xh,    g_xh);
    cudaGetSymbolAddress(&p_eah,   g_eah);
    cudaGetSymbolAddress(&p_wemb1, g_wemb1);
    cudaGetSymbolAddress(&p_wemb2, g_wemb2);
    cudaGetSymbolAddress(&p_wpq,   g_wpq);
    cudaGetSymbolAddress(&p_w1c,   g_w1c);
    cudaGetSymbolAddress(&p_wfu,   g_wfu);
    cudaGetSymbolAddress(&p_wu2,   g_wu2);
    cudaGetSymbolAddress(&p_w2u,   g_w2u);
    cudaGetSymbolAddress(&p_cvec,  g_cvec);
    cudaGetSymbolAddress(&p_pool,  g_pool);
    cudaGetSymbolAddress(&p_cnt,   g_cnt);

    // CSR + indeg
    k_detect<<<1, 256>>>(eidx);
    cudaMemsetAsync(p_ecnt, 0, NN * sizeof(int));
    k_hist<<<(NE + 255) / 256, 256>>>(eidx);
    k_scan<<<1, 1024>>>();
    k_fillcsr<<<(NE + 255) / 256, 256>>>(eidx);

    auto f2h = [&](const float* src, __half* dst, size_t n) {
        int n2 = (int)(n / 2);
        k_f2h<<<(n2 + 255) / 256, 256>>>((const float2*)src, (__half2*)dst, n2);
    };
    auto wt = [&](const float* W, __half* Wt, int K, int Nn) {
        int n = K * Nn;
        k_wt<<<(n + 255) / 256, 256>>>(W, Wt, K, Nn);
    };
    f2h(x,  (__half*)p_xh,  (size_t)NN * NFD);
    f2h(ea, (__half*)p_eah, (size_t)NE * EFD);
    wt(ew1, (__half*)p_wemb1, NFD, HH);
    wt(ew2, (__half*)p_wemb2, HH, HH);

    for (int l = 0; l < NL; l++) {
        const float* mw1l = mw1 + (size_t)l * (2 * HH + EFD) * HH;
        const float* uw1l = uw1 + (size_t)l * (2 * HH) * HH;
        __half* wpql = (__half*)p_wpq + (size_t)l * 2 * HH * HH;
        __half* w1cl = (__half*)p_w1c + (size_t)l * HH * EFD;
        __half* wful = (__half*)p_wfu + (size_t)l * HH * 2 * HH;
        __half* wu2l = (__half*)p_wu2 + (size_t)l * HH * HH;
        float*  cl   = (float*)p_cvec + (size_t)l * HH;
        // PQ weight: [0..255]=W1a^T, [256..511]=W1b^T
        wt(mw1l,            wpql,            HH, HH);
        wt(mw1l + HH * HH,  wpql + HH * HH,  HH, HH);
        wt(mw1l + 2 * HH * HH, w1cl, EFD, HH);
        // fused update weight
        dim3 b16(16, 16);
        k_w2u<<<dim3(16, 16), b16>>>(mw2 + (size_t)l * HH * HH, uw1l + HH * HH, (float*)p_w2u);
        k_packfu<<<(HH * 2 * HH + 255) / 256, 256>>>(uw1l, (const float*)p_w2u, wful);
        k_cvec<<<1, HH>>>(mb2 + l * HH, uw1l + HH * HH, cl);
        wt(uw2 + (size_t)l * HH * HH, wu2l, HH, HH);
    }

    dim3 gNode(157, 2);          // 20000 rows, N=256
    dim3 gPQ(157, 4);            // N=512
    dim3 gR(2500, 2);            // 320000 rows, N=256

    // embedder
    k_node<<<gNode, 256>>>((const __half*)p_xh, NFD, nullptr, 0,
                           (const __half*)p_wemb1, eb1, nullptr, nullptr,
                           (__half*)p_tmp, nullptr, HH, NN, 1);
    k_node<<<gNode, 256>>>((const __half*)p_tmp, HH, nullptr, 0,
                           (const __half*)p_wemb2, eb2, nullptr, nullptr,
                           (__half*)p_h, nullptr, HH, NN, 0);

    __half* hc = (__half*)p_h;
    __half* hn = (__half*)p_h2;

    for (int l = 0; l < NL; l++) {
        const __half* wpql = (const __half*)p_wpq + (size_t)l * 2 * HH * HH;
        const __half* w1cl = (const __half*)p_w1c + (size_t)l * HH * EFD;
        const __half* wful = (const __half*)p_wfu + (size_t)l * HH * 2 * HH;
        const __half* wu2l = (const __half*)p_wu2 + (size_t)l * HH * HH;
        const float*  cl   = (const float*)p_cvec + (size_t)l * HH;

        // PQ = h @ [W1a | W1b]   (fp32 out, ldc=512)
        k_node<<<gPQ, 256>>>(hc, HH, nullptr, 0, wpql, nullptr, nullptr, nullptr,
                             nullptr, (float*)p_PQ, 2 * HH, NN, 0);
        // R = ea @ W1c + b1      (fp32 out, ldc=256)
        k_node<<<gR, 256>>>((const __half*)p_eah, EFD, nullptr, 0, w1cl,
                            mb1 + l * HH, nullptr, nullptr,
                            nullptr, (float*)p_R, HH, NE, 0);
        // S[n] = sum_in relu(P[n]+Q[src]+R[e])  -> fp16
        k_gather<<<2500, 256>>>((const float*)p_PQ, (const float*)p_R, eidx, (__half*)p_Sh);
        // upd1 = relu( h@uw1_top + S@W2u + ub1 + indeg*c )
        k_node<<<gNode, 256>>>(hc, HH, (const __half*)p_Sh, HH, wful,
                               ub1 + l * HH, cl, (const float*)p_indeg,
                               (__half*)p_tmp, nullptr, HH, NN, 1);
        // upd2
        k_node<<<gNode, 256>>>((const __half*)p_tmp, HH, nullptr, 0, wu2l,
                               ub2 + l * HH, nullptr, nullptr,
                               hn, nullptr, HH, NN, 0);
        __half* t = hc; hc = hn; hn = t;
    }

    cudaMemsetAsync(p_pool, 0, (size_t)NG * HH * sizeof(float));
    cudaMemsetAsync(p_cnt,  0, (size_t)NG * sizeof(float));
    k_pool<<<(NN * HH + 255) / 256, 256>>>(hc, bat);
    k_head1<<<NG, HH>>>(hw1, hb1);
    k_head2<<<NG, OUTD>>>(hw2, hb2, out);
}

// round 9
// speedup vs baseline: 11.8013x; 1.1971x over previous
#include <cuda_runtime.h>
#include <cuda_fp16.h>
#include <cstdint>

// Problem constants
#define NN   20000
#define NE   320000
#define NFD  128
#define EFD  32
#define HH   256
#define OUTD 128
#define NL   4
#define NG   64

// GEMM tiling (fp16 mma.m16n8k16)
#define BM 128
#define BN 128
#define BK 32
#define STR 40             // smem row stride in halves (80 bytes)

// ---------------- scratch ----------------
__device__ __half g_h    [NN * HH];
__device__ __half g_h2   [NN * HH];
__device__ __half g_tmp  [NN * HH];
__device__ __half g_Sh   [NN * HH];
__device__ float  g_PQ   [NN * 2 * HH];         // [n][0:256]=P, [256:512]=Q
__device__ __half g_Rh   [(size_t)NE * HH];     // ea@W1c + b1 (fp16, 164MB)
__device__ float  g_indeg[NN];
__device__ int    g_ecnt [NN];
__device__ int    g_eoff [NN + 1];
__device__ int    g_ecur [NN];
__device__ int    g_eord [NE];
__device__ int    g_gcnt [NG];
__device__ int    g_goff [NG + 1];
__device__ __half g_xh   [NN * NFD];
__device__ __half g_eah  [(size_t)NE * EFD];
// transposed fp16 weights
__device__ __half g_wemb1[NFD * HH];
__device__ __half g_wemb2[HH * HH];
__device__ __half g_wpq  [NL][2 * HH * HH];     // [n(512)][k(256)]
__device__ __half g_w1c  [NL][HH * EFD];        // [n(256)][k(32)]
__device__ __half g_wfu  [NL][HH * 2 * HH];     // [n(256)][k(512)]
__device__ __half g_wu2  [NL][HH * HH];
__device__ float  g_w2u  [NL][HH * HH];
__device__ float  g_cvec [NL][HH];
__device__ float  g_pool [NG * HH];             // stores MEAN directly
__device__ float  g_t1   [NG * HH];
__device__ int    g_is64;

// ---------------- helpers ----------------
__device__ __forceinline__ void cpa16(uint32_t dst, const void* src) {
    asm volatile("cp.async.ca.shared.global [%0], [%1], 16;" :: "r"(dst), "l"(src));
}
#define CP_COMMIT asm volatile("cp.async.commit_group;")
#define CP_WAIT1  asm volatile("cp.async.wait_group 1;")

__device__ __forceinline__ int ldidx(const int* w, int is64, long i) {
    return is64 ? w[2 * i] : w[(size_t)i];
}

__device__ __forceinline__ uint4 ldcs16(const void* p) {
    uint4 v;
    asm volatile("ld.global.cs.v4.u32 {%0,%1,%2,%3}, [%4];"
        : "=r"(v.x), "=r"(v.y), "=r"(v.z), "=r"(v.w) : "l"(p));
    return v;
}
__device__ __forceinline__ void stcs2(__half2* p, __half2 v) {
    unsigned u = *reinterpret_cast<unsigned*>(&v);
    asm volatile("st.global.cs.u32 [%0], %1;" :: "l"(p), "r"(u));
}

__global__ void k_detect(const int* __restrict__ w) {
    __shared__ int nz;
    if (threadIdx.x == 0) nz = 0;
    __syncthreads();
    int local = 0;
    for (int i = 1 + 2 * threadIdx.x; i < 2 * NE; i += 2 * 256) local |= w[i];
    if (local) atomicOr(&nz, 1);
    __syncthreads();
    if (threadIdx.x == 0) g_is64 = (nz == 0) ? 1 : 0;
}

// ---------------- CSR build ----------------
__global__ void k_hist(const int* __restrict__ eidx) {
    int e = blockIdx.x * blockDim.x + threadIdx.x;
    if (e < NE) {
        int d = ldidx(eidx, g_is64, (long)NE + e);
        atomicAdd(&g_ecnt[d], 1);
    }
}

__global__ void k_scan() {     // 1 block, 1024 threads
    __shared__ int buf[1024];
    __shared__ int carry;
    int tid = threadIdx.x;
    if (tid == 0) carry = 0;
    __syncthreads();
    for (int base = 0; base < NN; base += 1024) {
        int v = (base + tid < NN) ? g_ecnt[base + tid] : 0;
        buf[tid] = v;
        __syncthreads();
        for (int s = 1; s < 1024; s <<= 1) {
            int t = (tid >= s) ? buf[tid - s] : 0;
            __syncthreads();
            buf[tid] += t;
            __syncthreads();
        }
        int excl = buf[tid] - v;
        if (base + tid < NN) {
            g_eoff[base + tid] = carry + excl;
            g_ecur[base + tid] = carry + excl;
            g_indeg[base + tid] = (float)v;
        }
        __syncthreads();
        if (tid == 1023) carry += buf[1023];
        __syncthreads();
    }
    if (tid == 0) g_eoff[NN] = carry;
}

__global__ void k_fillcsr(const int* __restrict__ eidx) {
    int e = blockIdx.x * blockDim.x + threadIdx.x;
    if (e < NE) {
        int d = ldidx(eidx, g_is64, (long)NE + e);
        int pos = atomicAdd(&g_ecur[d], 1);
        g_eord[pos] = e;
    }
}

// ---------------- graph (pool) offsets ----------------
__global__ void k_gcnt(const int* __restrict__ bat) {
    int n = blockIdx.x * blockDim.x + threadIdx.x;
    if (n < NN) atomicAdd(&g_gcnt[ldidx(bat, g_is64, n)], 1);
}
__global__ void k_goff() {     // 1 thread
    int run = 0;
    for (int g = 0; g < NG; g++) { g_goff[g] = run; run += g_gcnt[g]; }
    g_goff[NG] = run;
}

// ---------------- conversions / weight prep ----------------
__global__ void k_f2h(const float2* __restrict__ in, __half2* __restrict__ out, int n2) {
    int i = blockIdx.x * blockDim.x + threadIdx.x;
    if (i < n2) {
        float2 v = in[i];
        out[i] = __floats2half2_rn(v.x, v.y);
    }
}

// W[K][N] fp32 -> Wt[N][K] fp16 (single matrix)
__global__ void k_wt(const float* __restrict__ W, __half* __restrict__ Wt, int K, int N) {
    int i = blockIdx.x * blockDim.x + threadIdx.x;
    if (i < K * N) {
        int k = i / N, n = i - k * N;
        Wt[(size_t)n * K + k] = __float2half_rn(W[i]);
    }
}

// all-layer mw1 split: W1a^T -> wpq[:256], W1b^T -> wpq[256:], W1c^T -> w1c
__global__ void k_wt_mw1(const float* __restrict__ mw1) {
    int l = blockIdx.y;
    int i = blockIdx.x * blockDim.x + threadIdx.x;
    if (i >= (2 * HH + EFD) * HH) return;
    int k = i >> 8, n = i & 255;
    __half v = __float2half_rn(mw1[(size_t)l * (2 * HH + EFD) * HH + i]);
    if (k < HH)             g_wpq[l][n * HH + k] = v;
    else if (k < 2 * HH)    g_wpq[l][(HH + n) * HH + (k - HH)] = v;
    else                    g_w1c[l][n * EFD + (k - 2 * HH)] = v;
}

// all-layer uw2 transpose
__global__ void k_wt_uw2(const float* __restrict__ uw2) {
    int l = blockIdx.y;
    int i = blockIdx.x * blockDim.x + threadIdx.x;
    if (i >= HH * HH) return;
    int k = i >> 8, n = i & 255;
    g_wu2[l][n * HH + k] = __float2half_rn(uw2[(size_t)l * HH * HH + i]);
}

// W2u[l][k][n] = sum_j W2[l][k][j] * uw1b[l][j][n]
__global__ void k_w2u(const float* __restrict__ mw2, const float* __restrict__ uw1) {
    __shared__ float a[16][17], b[16][17];
    int l = blockIdx.z;
    const float* W2   = mw2 + (size_t)l * HH * HH;
    const float* uw1b = uw1 + (size_t)l * 2 * HH * HH + HH * HH;
    int ty = threadIdx.y, tx = threadIdx.x;
    int k = blockIdx.y * 16 + ty, n = blockIdx.x * 16 + tx;
    float s = 0.f;
    for (int j0 = 0; j0 < HH; j0 += 16) {
        a[ty][tx] = W2[k * HH + j0 + tx];
        b[ty][tx] = uw1b[(j0 + ty) * HH + n];
        __syncthreads();
#pragma unroll
        for (int j = 0; j < 16; j++) s += a[ty][j] * b[j][tx];
        __syncthreads();
    }
    g_w2u[l][k * HH + n] = s;
}

// pack fused update weight: Wfu[l][n][k] = k<256 ? uw1_top[k][n] : W2u[k-256][n]
__global__ void k_packfu(const float* __restrict__ uw1) {
    int l = blockIdx.y;
    int i = blockIdx.x * blockDim.x + threadIdx.x;
    if (i >= HH * 2 * HH) return;
    int n = i >> 9, k = i & 511;
    const float* uw1l = uw1 + (size_t)l * 2 * HH * HH;
    float v = (k < HH) ? uw1l[k * HH + n] : g_w2u[l][(k - HH) * HH + n];
    g_wfu[l][n * (2 * HH) + k] = __float2half_rn(v);
}

// c[l][n] = sum_j b2[l][j] * uw1b[l][j][n]
__global__ void k_cvec(const float* __restrict__ mb2, const float* __restrict__ uw1) {
    int l = blockIdx.x, n = threadIdx.x;
    const float* b2   = mb2 + (size_t)l * HH;
    const float* uw1b = uw1 + (size_t)l * 2 * HH * HH + HH * HH;
    float s = 0.f;
    for (int j = 0; j < HH; j++) s += b2[j] * uw1b[j * HH + n];
    g_cvec[l][n] = s;
}

// ---------------- fp16 tensor-core GEMM ----------------
__device__ __forceinline__ void mma16(float* c, const unsigned* a, const unsigned* b) {
    asm volatile(
        "mma.sync.aligned.m16n8k16.row.col.f32.f16.f16.f32 "
        "{%0,%1,%2,%3},{%4,%5,%6,%7},{%8,%9},{%0,%1,%2,%3};"
        : "+f"(c[0]), "+f"(c[1]), "+f"(c[2]), "+f"(c[3])
        : "r"(a[0]), "r"(a[1]), "r"(a[2]), "r"(a[3]), "r"(b[0]), "r"(b[1]));
}

__device__ __forceinline__ void ldm4(unsigned* r, uint32_t addr) {
    asm volatile("ldmatrix.sync.aligned.m8n8.x4.shared.b16 {%0,%1,%2,%3}, [%4];"
        : "=r"(r[0]), "=r"(r[1]), "=r"(r[2]), "=r"(r[3]) : "r"(addr));
}

__device__ __forceinline__ void mma_chunk(
    uint32_t As, uint32_t Bs, float acc[4][4][4], int wm, int wn, int lane)
{
    const int i8 = lane & 7, q = lane >> 3;
    const int aRow = (q & 1) * 8 + i8;
    const int aCol = (q >> 1) * 8;
    const int bRow = (q >> 1) * 8 + i8;
    const int bCol = (q & 1) * 8;
#pragma unroll
    for (int s = 0; s < 2; s++) {
        unsigned afr[4][4];
#pragma unroll
        for (int tm = 0; tm < 4; tm++)
            ldm4(afr[tm], As + ((wm * 64 + tm * 16 + aRow) * STR + s * 16 + aCol) * 2);
        unsigned btmp[2][4];
#pragma unroll
        for (int p = 0; p < 2; p++)
            ldm4(btmp[p], Bs + ((wn * 32 + p * 16 + bRow) * STR + s * 16 + bCol) * 2);
#pragma unroll
        for (int tm = 0; tm < 4; tm++) {
#pragma unroll
            for (int p = 0; p < 2; p++) {
                unsigned b0[2] = { btmp[p][0], btmp[p][1] };
                unsigned b1[2] = { btmp[p][2], btmp[p][3] };
                mma16(acc[tm][2 * p],     afr[tm], b0);
                mma16(acc[tm][2 * p + 1], afr[tm], b1);
            }
        }
    }
}

__device__ __forceinline__ void fill_B(uint32_t bs, const __half* __restrict__ Wt,
                                       int Kstride, int ch, int n0, int tid) {
#pragma unroll
    for (int j = 0; j < 2; j++) {
        int v = tid + 256 * j;
        int r = v >> 2, c8 = v & 3;
        cpa16(bs + r * (STR * 2) + c8 * 16,
              Wt + (size_t)(n0 + r) * Kstride + ch * BK + c8 * 8);
    }
}

#define ACC_INIT \
    float acc[4][4][4]; \
    _Pragma("unroll") for (int a_ = 0; a_ < 4; a_++) \
    _Pragma("unroll") for (int b_ = 0; b_ < 4; b_++) \
    _Pragma("unroll") for (int c_ = 0; c_ < 4; c_++) acc[a_][b_][c_] = 0.f;

// Generic GEMM: C = act( [A1|A2] @ Wt^T + bias + rowScale*bias2 )
__global__ void __launch_bounds__(256, 2)
k_node(const __half* __restrict__ A1, int K1,
       const __half* __restrict__ A2, int K2,
       const __half* __restrict__ Wt, const float* __restrict__ bias,
       const float* __restrict__ bias2, const float* __restrict__ rowScale,
       __half* __restrict__ Ch, float* __restrict__ Cf, int ldc,
       int M, int doRelu, int streamC)
{
    __shared__ __align__(16) __half As[2][BM * STR];
    __shared__ __align__(16) __half Bs[2][BN * STR];
    __shared__ float sBias[BN], sBias2[BN];

    const int tid = threadIdx.x, lane = tid & 31, warp = tid >> 5;
    const int wm = warp & 1, wn = warp >> 1;
    const int m0 = blockIdx.x * BM;
    const int n0 = blockIdx.y * BN;
    const int K = K1 + K2;
    const int NCH = K / BK;

    if (tid < BM) {
        sBias[tid]  = bias  ? bias[n0 + tid]  : 0.f;
        sBias2[tid] = bias2 ? bias2[n0 + tid] : 0.f;
    }
    __syncthreads();

    uint32_t asb[2] = { (uint32_t)__cvta_generic_to_shared(As[0]),
                        (uint32_t)__cvta_generic_to_shared(As[1]) };
    uint32_t bsb[2] = { (uint32_t)__cvta_generic_to_shared(Bs[0]),
                        (uint32_t)__cvta_generic_to_shared(Bs[1]) };

    ACC_INIT;

    auto fillA = [&](uint32_t as, int ch) {
        int k0 = ch * BK;
#pragma unroll
        for (int j = 0; j < 2; j++) {
            int v = tid + 256 * j;
            int r = v >> 2, c8 = v & 3;
            int gr = m0 + r;
            if (gr >= M) gr = M - 1;
            int gc = k0 + c8 * 8;
            const __half* p = (gc < K1) ? A1 + (size_t)gr * K1 + gc
                                        : A2 + (size_t)gr * K2 + (gc - K1);
            cpa16(as + r * (STR * 2) + c8 * 16, p);
        }
    };

    fillA(asb[0], 0);
    fill_B(bsb[0], Wt, K, 0, n0, tid);
    CP_COMMIT;

#pragma unroll 1
    for (int ch = 0; ch < NCH; ch++) {
        int cur = ch & 1, nxt = cur ^ 1;
        if (ch + 1 < NCH) {
            fillA(asb[nxt], ch + 1);
            fill_B(bsb[nxt], Wt, K, ch + 1, n0, tid);
        }
        CP_COMMIT;
        CP_WAIT1;
        __syncthreads();
        mma_chunk(asb[cur], bsb[cur], acc, wm, wn, lane);
        __syncthreads();
    }

#pragma unroll
    for (int tm = 0; tm < 4; tm++) {
        int mr = m0 + wm * 64 + tm * 16 + (lane >> 2);
        float sc0 = 0.f, sc1 = 0.f;
        if (rowScale) {
            sc0 = rowScale[mr < M ? mr : M - 1];
            sc1 = rowScale[(mr + 8) < M ? (mr + 8) : M - 1];
        }
#pragma unroll
        for (int tn = 0; tn < 4; tn++) {
            int ncl = wn * 32 + tn * 8 + 2 * (lane & 3);
            float b0 = sBias[ncl], b1 = sBias[ncl + 1];
            float c0 = sBias2[ncl], c1 = sBias2[ncl + 1];
            float v0 = acc[tm][tn][0] + b0 + sc0 * c0;
            float v1 = acc[tm][tn][1] + b1 + sc0 * c1;
            float v2 = acc[tm][tn][2] + b0 + sc1 * c0;
            float v3 = acc[tm][tn][3] + b1 + sc1 * c1;
            if (doRelu) {
                v0 = fmaxf(v0, 0.f); v1 = fmaxf(v1, 0.f);
                v2 = fmaxf(v2, 0.f); v3 = fmaxf(v3, 0.f);
            }
            if (Cf) {
                if (mr < M) {
                    float2 o; o.x = v0; o.y = v1;
                    *reinterpret_cast<float2*>(Cf + (size_t)mr * ldc + n0 + ncl) = o;
                }
                if (mr + 8 < M) {
                    float2 o; o.x = v2; o.y = v3;
                    *reinterpret_cast<float2*>(Cf + (size_t)(mr + 8) * ldc + n0 + ncl) = o;
                }
            } else if (streamC) {
                if (mr < M)
                    stcs2(reinterpret_cast<__half2*>(Ch + (size_t)mr * ldc + n0 + ncl),
                          __floats2half2_rn(v0, v1));
                if (mr + 8 < M)
                    stcs2(reinterpret_cast<__half2*>(Ch + (size_t)(mr + 8) * ldc + n0 + ncl),
                          __floats2half2_rn(v2, v3));
            } else {
                if (mr < M)
                    *reinterpret_cast<__half2*>(Ch + (size_t)mr * ldc + n0 + ncl) =
                        __floats2half2_rn(v0, v1);
                if (mr + 8 < M)
                    *reinterpret_cast<__half2*>(Ch + (size_t)(mr + 8) * ldc + n0 + ncl) =
                        __floats2half2_rn(v2, v3);
            }
        }
    }
}

// ---------------- gather: S[n] = sum_{e in in(n)} relu(P[n]+Q[src]+R[e]) ---------
__global__ void __launch_bounds__(256)
k_gather(const float* __restrict__ PQ, const __half* __restrict__ Rh,
         const int* __restrict__ eidx, __half* __restrict__ Sh)
{
    int n = blockIdx.x * 8 + (threadIdx.x >> 5);
    int lane = threadIdx.x & 31;
    if (n >= NN) return;
    int c0 = lane * 8;
    const int is64 = g_is64;

    float4 pa = *(const float4*)(PQ + (size_t)n * 512 + c0);
    float4 pb = *(const float4*)(PQ + (size_t)n * 512 + c0 + 4);
    float acc0 = 0.f, acc1 = 0.f, acc2 = 0.f, acc3 = 0.f;
    float acc4 = 0.f, acc5 = 0.f, acc6 = 0.f, acc7 = 0.f;

    int i = g_eoff[n], end = g_eoff[n + 1];
    for (; i < end; i++) {
        int e = g_eord[i];
        int s = ldidx(eidx, is64, e);
        float4 qa = *(const float4*)(PQ + (size_t)s * 512 + 256 + c0);
        float4 qb = *(const float4*)(PQ + (size_t)s * 512 + 256 + c0 + 4);
        uint4 rv = ldcs16(Rh + (size_t)e * HH + c0);
        float2 r01 = __half22float2(*reinterpret_cast<__half2*>(&rv.x));
        float2 r23 = __half22float2(*reinterpret_cast<__half2*>(&rv.y));
        float2 r45 = __half22float2(*reinterpret_cast<__half2*>(&rv.z));
        float2 r67 = __half22float2(*reinterpret_cast<__half2*>(&rv.w));
        acc0 += fmaxf(pa.x + qa.x + r01.x, 0.f);
        acc1 += fmaxf(pa.y + qa.y + r01.y, 0.f);
        acc2 += fmaxf(pa.z + qa.z + r23.x, 0.f);
        acc3 += fmaxf(pa.w + qa.w + r23.y, 0.f);
        acc4 += fmaxf(pb.x + qb.x + r45.x, 0.f);
        acc5 += fmaxf(pb.y + qb.y + r45.y, 0.f);
        acc6 += fmaxf(pb.z + qb.z + r67.x, 0.f);
        acc7 += fmaxf(pb.w + qb.w + r67.y, 0.f);
    }

    __half2* o = reinterpret_cast<__half2*>(Sh + (size_t)n * HH + c0);
    o[0] = __floats2half2_rn(acc0, acc1);
    o[1] = __floats2half2_rn(acc2, acc3);
    o[2] = __floats2half2_rn(acc4, acc5);
    o[3] = __floats2half2_rn(acc6, acc7);
}

// ---------------- pooling (sorted batch -> segment mean) ----------------
__global__ void k_pool(const __half* __restrict__ h) {
    int g = blockIdx.x, t = threadIdx.x;
    int r0 = g_goff[g], r1 = g_goff[g + 1];
    float acc = 0.f;
    for (int r = r0; r < r1; r++)
        acc += __half2float(h[(size_t)r * HH + t]);
    float cnt = (float)(r1 - r0);
    g_pool[g * HH + t] = acc / fmaxf(cnt, 1.0f);
}

// ---------------- head ----------------
__global__ void k_head1(const float* __restrict__ hw1, const float* __restrict__ hb1) {
    __shared__ float p[HH];
    int g = blockIdx.x;
    int t = threadIdx.x;
    p[t] = g_pool[g * HH + t];
    __syncthreads();
    float s = hb1[t];
    for (int k = 0; k < HH; k++) s += p[k] * hw1[k * HH + t];
    g_t1[g * HH + t] = fmaxf(s, 0.f);
}

__global__ void k_head2(const float* __restrict__ hw2, const float* __restrict__ hb2,
                        float* __restrict__ out) {
    __shared__ float q[HH];
    int g = blockIdx.x;
    int t = threadIdx.x;
    q[t] = g_t1[g * HH + t];
    q[t + 128] = g_t1[g * HH + t + 128];
    __syncthreads();
    float s = hb2[t];
    for (int k = 0; k < HH; k++) s += q[k] * hw2[k * OUTD + t];
    out[g * OUTD + t] = s;
}

// ---------------- launcher ----------------
extern "C" void kernel_launch(void* const* d_in, const int* in_sizes, int n_in,
                              void* d_out, int out_size)
{
    const float* x    = (const float*)d_in[0];
    const float* ea   = (const float*)d_in[1];
    const float* ew1  = (const float*)d_in[2];
    const float* eb1  = (const float*)d_in[3];
    const float* ew2  = (const float*)d_in[4];
    const float* eb2  = (const float*)d_in[5];
    const float* mw1  = (const float*)d_in[6];
    const float* mb1  = (const float*)d_in[7];
    const float* mw2  = (const float*)d_in[8];
    const float* mb2  = (const float*)d_in[9];
    const float* uw1  = (const float*)d_in[10];
    const float* ub1  = (const float*)d_in[11];
    const float* uw2  = (const float*)d_in[12];
    const float* ub2  = (const float*)d_in[13];
    const float* hw1  = (const float*)d_in[14];
    const float* hb1  = (const float*)d_in[15];
    const float* hw2  = (const float*)d_in[16];
    const float* hb2  = (const float*)d_in[17];
    const int*   eidx = (const int*)d_in[18];
    const int*   bat  = (const int*)d_in[19];
    float* out = (float*)d_out;

    void *p_h, *p_h2, *p_tmp, *p_Sh, *p_PQ, *p_Rh, *p_indeg, *p_ecnt, *p_gcnt;
    void *p_xh, *p_eah, *p_wemb1, *p_wemb2, *p_wpq, *p_w1c, *p_wfu, *p_wu2, *p_cvec;
    cudaGetSymbolAddress(&p_h,     g_h);
    cudaGetSymbolAddress(&p_h2,    g_h2);
    cudaGetSymbolAddress(&p_tmp,   g_tmp);
    cudaGetSymbolAddress(&p_Sh,    g_Sh);
    cudaGetSymbolAddress(&p_PQ,    g_PQ);
    cudaGetSymbolAddress(&p_Rh,    g_Rh);
    cudaGetSymbolAddress(&p_indeg, g_indeg);
    cudaGetSymbolAddress(&p_ecnt,  g_ecnt);
    cudaGetSymbolAddress(&p_gcnt,  g_gcnt);
    cudaGetSymbolAddress(&p_xh,    g_xh);
    cudaGetSymbolAddress(&p_eah,   g_eah);
    cudaGetSymbolAddress(&p_wemb1, g_wemb1);
    cudaGetSymbolAddress(&p_wemb2, g_wemb2);
    cudaGetSymbolAddress(&p_wpq,   g_wpq);
    cudaGetSymbolAddress(&p_w1c,   g_w1c);
    cudaGetSymbolAddress(&p_wfu,   g_wfu);
    cudaGetSymbolAddress(&p_wu2,   g_wu2);
    cudaGetSymbolAddress(&p_cvec,  g_cvec);

    // CSR + indeg + graph offsets
    k_detect<<<1, 256>>>(eidx);
    cudaMemsetAsync(p_ecnt, 0, NN * sizeof(int));
    cudaMemsetAsync(p_gcnt, 0, NG * sizeof(int));
    k_hist<<<(NE + 255) / 256, 256>>>(eidx);
    k_scan<<<1, 1024>>>();
    k_fillcsr<<<(NE + 255) / 256, 256>>>(eidx);
    k_gcnt<<<(NN + 255) / 256, 256>>>(bat);
    k_goff<<<1, 1>>>();

    auto f2h = [&](const float* src, __half* dst, size_t n) {
        int n2 = (int)(n / 2);
        k_f2h<<<(n2 + 255) / 256, 256>>>((const float2*)src, (__half2*)dst, n2);
    };
    f2h(x,  (__half*)p_xh,  (size_t)NN * NFD);
    f2h(ea, (__half*)p_eah, (size_t)NE * EFD);
    k_wt<<<(NFD * HH + 255) / 256, 256>>>(ew1, (__half*)p_wemb1, NFD, HH);
    k_wt<<<(HH * HH + 255) / 256, 256>>>(ew2, (__half*)p_wemb2, HH, HH);
    k_wt_mw1<<<dim3(((2 * HH + EFD) * HH + 255) / 256, NL), 256>>>(mw1);
    k_wt_uw2<<<dim3((HH * HH + 255) / 256, NL), 256>>>(uw2);
    k_w2u<<<dim3(16, 16, NL), dim3(16, 16)>>>(mw2, uw1);
    k_packfu<<<dim3((HH * 2 * HH + 255) / 256, NL), 256>>>(uw1);
    k_cvec<<<NL, HH>>>(mb2, uw1);

    dim3 gNode(157, 2);          // 20000 rows, N=256
    dim3 gPQ(157, 4);            // N=512
    dim3 gR(2500, 2);            // 320000 rows, N=256

    // embedder
    k_node<<<gNode, 256>>>((const __half*)p_xh, NFD, nullptr, 0,
                           (const __half*)p_wemb1, eb1, nullptr, nullptr,
                           (__half*)p_tmp, nullptr, HH, NN, 1, 0);
    k_node<<<gNode, 256>>>((const __half*)p_tmp, HH, nullptr, 0,
                           (const __half*)p_wemb2, eb2, nullptr, nullptr,
                           (__half*)p_h, nullptr, HH, NN, 0, 0);

    __half* hc = (__half*)p_h;
    __half* hn = (__half*)p_h2;

    for (int l = 0; l < NL; l++) {
        const __half* wpql = (const __half*)p_wpq + (size_t)l * 2 * HH * HH;
        const __half* w1cl = (const __half*)p_w1c + (size_t)l * HH * EFD;
        const __half* wful = (const __half*)p_wfu + (size_t)l * HH * 2 * HH;
        const __half* wu2l = (const __half*)p_wu2 + (size_t)l * HH * HH;
        const float*  cl   = (const float*)p_cvec + (size_t)l * HH;

        // PQ = h @ [W1a | W1b]   (fp32 out, ldc=512)
        k_node<<<gPQ, 256>>>(hc, HH, nullptr, 0, wpql, nullptr, nullptr, nullptr,
                             nullptr, (float*)p_PQ, 2 * HH, NN, 0, 0);
        // R = ea @ W1c + b1      (fp16 out, streaming stores)
        k_node<<<gR, 256>>>((const __half*)p_eah, EFD, nullptr, 0, w1cl,
                            mb1 + l * HH, nullptr, nullptr,
                            (__half*)p_Rh, nullptr, HH, NE, 0, 1);
        // S[n] = sum_in relu(P[n]+Q[src]+R[e])  -> fp16
        k_gather<<<2500, 256>>>((const float*)p_PQ, (const __half*)p_Rh, eidx,
                                (__half*)p_Sh);
        // upd1 = relu( h@uw1_top + S@W2u + ub1 + indeg*c )
        k_node<<<gNode, 256>>>(hc, HH, (const __half*)p_Sh, HH, wful,
                               ub1 + l * HH, cl, (const float*)p_indeg,
                               (__half*)p_tmp, nullptr, HH, NN, 1, 0);
        // upd2
        k_node<<<gNode, 256>>>((const __half*)p_tmp, HH, nullptr, 0, wu2l,
                               ub2 + l * HH, nullptr, nullptr,
                               hn, nullptr, HH, NN, 0, 0);
        __half* t = hc; hc = hn; hn = t;
    }

    k_pool<<<NG, HH>>>(hc);
    k_head1<<<NG, HH>>>(hw1, hb1);
    k_head2<<<NG, OUTD>>>(hw2, hb2, out);
}

// round 11
// speedup vs baseline: 12.4777x; 1.0573x over previous
#include <cuda_runtime.h>
#include <cuda_fp16.h>
#include <cstdint>

// Problem constants
#define NN   20000
#define NE   320000
#define NFD  128
#define EFD  32
#define HH   256
#define OUTD 128
#define NL   4
#define NG   64

// GEMM tiling (fp16 mma.m16n8k16)
#define BM 128
#define BN 128
#define BK 32
#define STR 40             // smem row stride in halves (80 bytes)

// ---------------- scratch ----------------
__device__ __half g_h    [NN * HH];
__device__ __half g_h2   [NN * HH];
__device__ __half g_tmp  [NN * HH];
__device__ __half g_Sh   [NN * HH];
__device__ __half g_PQh  [NN * 2 * HH];         // [n][0:256]=P, [256:512]=Q (fp16)
__device__ __half g_Rh   [(size_t)NE * HH];     // CSR-ordered R (fp16, 164MB)
__device__ float  g_indeg[NN];
__device__ int    g_ecnt [NN];
__device__ int    g_eoff [NN + 1];
__device__ int    g_ecur [NN];
__device__ int    g_eord [NE];
__device__ int    g_srccsr[NE];
__device__ __half g_eacsr[(size_t)NE * EFD];    // CSR-ordered edge_attr fp16
__device__ int    g_gcnt [NG];
__device__ int    g_goff [NG + 1];
__device__ __half g_xh   [NN * NFD];
// transposed fp16 weights
__device__ __half g_wemb1[NFD * HH];
__device__ __half g_wemb2[HH * HH];
__device__ __half g_wpq  [NL][2 * HH * HH];     // [n(512)][k(256)]
__device__ __half g_w1c  [NL][HH * EFD];        // [n(256)][k(32)]
__device__ __half g_wfu  [NL][HH * 2 * HH];     // [n(256)][k(512)]
__device__ __half g_wu2  [NL][HH * HH];
__device__ float  g_w2u  [NL][HH * HH];
__device__ float  g_cvec [NL][HH];
__device__ float  g_pool [NG * HH];             // stores MEAN directly
__device__ float  g_t1   [NG * HH];
__device__ int    g_is64;

// ---------------- helpers ----------------
__device__ __forceinline__ void cpa16(uint32_t dst, const void* src) {
    asm volatile("cp.async.ca.shared.global [%0], [%1], 16;" :: "r"(dst), "l"(src));
}
#define CP_COMMIT asm volatile("cp.async.commit_group;")
#define CP_WAIT1  asm volatile("cp.async.wait_group 1;")

__device__ __forceinline__ int ldidx(const int* w, int is64, long i) {
    return is64 ? w[2 * i] : w[(size_t)i];
}

__device__ __forceinline__ uint4 ldcs16(const void* p) {
    uint4 v;
    asm volatile("ld.global.cs.v4.u32 {%0,%1,%2,%3}, [%4];"
        : "=r"(v.x), "=r"(v.y), "=r"(v.z), "=r"(v.w) : "l"(p));
    return v;
}
__device__ __forceinline__ void stcs2(__half2* p, __half2 v) {
    unsigned u = *reinterpret_cast<unsigned*>(&v);
    asm volatile("st.global.cs.u32 [%0], %1;" :: "l"(p), "r"(u));
}

__global__ void k_detect(const int* __restrict__ w) {
    __shared__ int nz;
    if (threadIdx.x == 0) nz = 0;
    __syncthreads();
    int local = 0;
    for (int i = 1 + 2 * threadIdx.x; i < 2 * NE; i += 2 * 256) local |= w[i];
    if (local) atomicOr(&nz, 1);
    __syncthreads();
    if (threadIdx.x == 0) g_is64 = (nz == 0) ? 1 : 0;
}

// ---------------- CSR build ----------------
__global__ void k_hist(const int* __restrict__ eidx) {
    int e = blockIdx.x * blockDim.x + threadIdx.x;
    if (e < NE) {
        int d = ldidx(eidx, g_is64, (long)NE + e);
        atomicAdd(&g_ecnt[d], 1);
    }
}

__global__ void k_scan() {     // 1 block, 1024 threads
    __shared__ int buf[1024];
    __shared__ int carry;
    int tid = threadIdx.x;
    if (tid == 0) carry = 0;
    __syncthreads();
    for (int base = 0; base < NN; base += 1024) {
        int v = (base + tid < NN) ? g_ecnt[base + tid] : 0;
        buf[tid] = v;
        __syncthreads();
        for (int s = 1; s < 1024; s <<= 1) {
            int t = (tid >= s) ? buf[tid - s] : 0;
            __syncthreads();
            buf[tid] += t;
            __syncthreads();
        }
        int excl = buf[tid] - v;
        if (base + tid < NN) {
            g_eoff[base + tid] = carry + excl;
            g_ecur[base + tid] = carry + excl;
            g_indeg[base + tid] = (float)v;
        }
        __syncthreads();
        if (tid == 1023) carry += buf[1023];
        __syncthreads();
    }
    if (tid == 0) g_eoff[NN] = carry;
}

__global__ void k_fillcsr(const int* __restrict__ eidx) {
    int e = blockIdx.x * blockDim.x + threadIdx.x;
    if (e < NE) {
        int d = ldidx(eidx, g_is64, (long)NE + e);
        int pos = atomicAdd(&g_ecur[d], 1);
        g_eord[pos] = e;
    }
}

// permute edge_attr + src into CSR order (converts ea fp32 -> fp16)
__global__ void k_permute(const float* __restrict__ ea, const int* __restrict__ eidx) {
    int idx = blockIdx.x * blockDim.x + threadIdx.x;   // NE * 16
    if (idx >= NE * 16) return;
    int i = idx >> 4, c = idx & 15;
    int e = g_eord[i];
    float2 v = *(const float2*)(ea + (size_t)e * EFD + 2 * c);
    *reinterpret_cast<__half2*>(g_eacsr + (size_t)i * EFD + 2 * c) =
        __floats2half2_rn(v.x, v.y);
    if (c == 0) g_srccsr[i] = ldidx(eidx, g_is64, e);
}

// ---------------- graph (pool) offsets ----------------
__global__ void k_gcnt(const int* __restrict__ bat) {
    int n = blockIdx.x * blockDim.x + threadIdx.x;
    if (n < NN) atomicAdd(&g_gcnt[ldidx(bat, g_is64, n)], 1);
}
__global__ void k_goff() {     // 1 thread
    int run = 0;
    for (int g = 0; g < NG; g++) { g_goff[g] = run; run += g_gcnt[g]; }
    g_goff[NG] = run;
}

// ---------------- conversions / weight prep ----------------
__global__ void k_f2h(const float2* __restrict__ in, __half2* __restrict__ out, int n2) {
    int i = blockIdx.x * blockDim.x + threadIdx.x;
    if (i < n2) {
        float2 v = in[i];
        out[i] = __floats2half2_rn(v.x, v.y);
    }
}

// W[K][N] fp32 -> Wt[N][K] fp16 (single matrix)
__global__ void k_wt(const float* __restrict__ W, __half* __restrict__ Wt, int K, int N) {
    int i = blockIdx.x * blockDim.x + threadIdx.x;
    if (i < K * N) {
        int k = i / N, n = i - k * N;
        Wt[(size_t)n * K + k] = __float2half_rn(W[i]);
    }
}

// all-layer mw1 split: W1a^T -> wpq[:256], W1b^T -> wpq[256:], W1c^T -> w1c
__global__ void k_wt_mw1(const float* __restrict__ mw1) {
    int l = blockIdx.y;
    int i = blockIdx.x * blockDim.x + threadIdx.x;
    if (i >= (2 * HH + EFD) * HH) return;
    int k = i >> 8, n = i & 255;
    __half v = __float2half_rn(mw1[(size_t)l * (2 * HH + EFD) * HH + i]);
    if (k < HH)             g_wpq[l][n * HH + k] = v;
    else if (k < 2 * HH)    g_wpq[l][(HH + n) * HH + (k - HH)] = v;
    else                    g_w1c[l][n * EFD + (k - 2 * HH)] = v;
}

// all-layer uw2 transpose
__global__ void k_wt_uw2(const float* __restrict__ uw2) {
    int l = blockIdx.y;
    int i = blockIdx.x * blockDim.x + threadIdx.x;
    if (i >= HH * HH) return;
    int k = i >> 8, n = i & 255;
    g_wu2[l][n * HH + k] = __float2half_rn(uw2[(size_t)l * HH * HH + i]);
}

// W2u[l][k][n] = sum_j W2[l][k][j] * uw1b[l][j][n]
__global__ void k_w2u(const float* __restrict__ mw2, const float* __restrict__ uw1) {
    __shared__ float a[16][17], b[16][17];
    int l = blockIdx.z;
    const float* W2   = mw2 + (size_t)l * HH * HH;
    const float* uw1b = uw1 + (size_t)l * 2 * HH * HH + HH * HH;
    int ty = threadIdx.y, tx = threadIdx.x;
    int k = blockIdx.y * 16 + ty, n = blockIdx.x * 16 + tx;
    float s = 0.f;
    for (int j0 = 0; j0 < HH; j0 += 16) {
        a[ty][tx] = W2[k * HH + j0 + tx];
        b[ty][tx] = uw1b[(j0 + ty) * HH + n];
        __syncthreads();
#pragma unroll
        for (int j = 0; j < 16; j++) s += a[ty][j] * b[j][tx];
        __syncthreads();
    }
    g_w2u[l][k * HH + n] = s;
}

// pack fused update weight: Wfu[l][n][k] = k<256 ? uw1_top[k][n] : W2u[k-256][n]
__global__ void k_packfu(const float* __restrict__ uw1) {
    int l = blockIdx.y;
    int i = blockIdx.x * blockDim.x + threadIdx.x;
    if (i >= HH * 2 * HH) return;
    int n = i >> 9, k = i & 511;
    const float* uw1l = uw1 + (size_t)l * 2 * HH * HH;
    float v = (k < HH) ? uw1l[k * HH + n] : g_w2u[l][(k - HH) * HH + n];
    g_wfu[l][n * (2 * HH) + k] = __float2half_rn(v);
}

// c[l][n] = sum_j b2[l][j] * uw1b[l][j][n]
__global__ void k_cvec(const float* __restrict__ mb2, const float* __restrict__ uw1) {
    int l = blockIdx.x, n = threadIdx.x;
    const float* b2   = mb2 + (size_t)l * HH;
    const float* uw1b = uw1 + (size_t)l * 2 * HH * HH + HH * HH;
    float s = 0.f;
    for (int j = 0; j < HH; j++) s += b2[j] * uw1b[j * HH + n];
    g_cvec[l][n] = s;
}

// ---------------- fp16 tensor-core GEMM ----------------
__device__ __forceinline__ void mma16(float* c, const unsigned* a, const unsigned* b) {
    asm volatile(
        "mma.sync.aligned.m16n8k16.row.col.f32.f16.f16.f32 "
        "{%0,%1,%2,%3},{%4,%5,%6,%7},{%8,%9},{%0,%1,%2,%3};"
        : "+f"(c[0]), "+f"(c[1]), "+f"(c[2]), "+f"(c[3])
        : "r"(a[0]), "r"(a[1]), "r"(a[2]), "r"(a[3]), "r"(b[0]), "r"(b[1]));
}

__device__ __forceinline__ void ldm4(unsigned* r, uint32_t addr) {
    asm volatile("ldmatrix.sync.aligned.m8n8.x4.shared.b16 {%0,%1,%2,%3}, [%4];"
        : "=r"(r[0]), "=r"(r[1]), "=r"(r[2]), "=r"(r[3]) : "r"(addr));
}

__device__ __forceinline__ void mma_chunk(
    uint32_t As, uint32_t Bs, float acc[4][4][4], int wm, int wn, int lane)
{
    const int i8 = lane & 7, q = lane >> 3;
    const int aRow = (q & 1) * 8 + i8;
    const int aCol = (q >> 1) * 8;
    const int bRow = (q >> 1) * 8 + i8;
    const int bCol = (q & 1) * 8;
#pragma unroll
    for (int s = 0; s < 2; s++) {
        unsigned afr[4][4];
#pragma unroll
        for (int tm = 0; tm < 4; tm++)
            ldm4(afr[tm], As + ((wm * 64 + tm * 16 + aRow) * STR + s * 16 + aCol) * 2);
        unsigned btmp[2][4];
#pragma unroll
        for (int p = 0; p < 2; p++)
            ldm4(btmp[p], Bs + ((wn * 32 + p * 16 + bRow) * STR + s * 16 + bCol) * 2);
#pragma unroll
        for (int tm = 0; tm < 4; tm++) {
#pragma unroll
            for (int p = 0; p < 2; p++) {
                unsigned b0[2] = { btmp[p][0], btmp[p][1] };
                unsigned b1[2] = { btmp[p][2], btmp[p][3] };
                mma16(acc[tm][2 * p],     afr[tm], b0);
                mma16(acc[tm][2 * p + 1], afr[tm], b1);
            }
        }
    }
}

__device__ __forceinline__ void fill_B(uint32_t bs, const __half* __restrict__ Wt,
                                       int Kstride, int ch, int n0, int tid) {
#pragma unroll
    for (int j = 0; j < 2; j++) {
        int v = tid + 256 * j;
        int r = v >> 2, c8 = v & 3;
        cpa16(bs + r * (STR * 2) + c8 * 16,
              Wt + (size_t)(n0 + r) * Kstride + ch * BK + c8 * 8);
    }
}

#define ACC_INIT \
    float acc[4][4][4]; \
    _Pragma("unroll") for (int a_ = 0; a_ < 4; a_++) \
    _Pragma("unroll") for (int b_ = 0; b_ < 4; b_++) \
    _Pragma("unroll") for (int c_ = 0; c_ < 4; c_++) acc[a_][b_][c_] = 0.f;

// Generic GEMM: C = act( [A1|A2] @ Wt^T + bias + rowScale*bias2 )  (fp16 out)
__global__ void __launch_bounds__(256, 2)
k_node(const __half* __restrict__ A1, int K1,
       const __half* __restrict__ A2, int K2,
       const __half* __restrict__ Wt, const float* __restrict__ bias,
       const float* __restrict__ bias2, const float* __restrict__ rowScale,
       __half* __restrict__ Ch, int ldc,
       int M, int doRelu, int streamC)
{
    __shared__ __align__(16) __half As[2][BM * STR];
    __shared__ __align__(16) __half Bs[2][BN * STR];
    __shared__ float sBias[BN], sBias2[BN];

    const int tid = threadIdx.x, lane = tid & 31, warp = tid >> 5;
    const int wm = warp & 1, wn = warp >> 1;
    const int m0 = blockIdx.x * BM;
    const int n0 = blockIdx.y * BN;
    const int K = K1 + K2;
    const int NCH = K / BK;

    if (tid < BM) {
        sBias[tid]  = bias  ? bias[n0 + tid]  : 0.f;
        sBias2[tid] = bias2 ? bias2[n0 + tid] : 0.f;
    }
    __syncthreads();

    uint32_t asb[2] = { (uint32_t)__cvta_generic_to_shared(As[0]),
                        (uint32_t)__cvta_generic_to_shared(As[1]) };
    uint32_t bsb[2] = { (uint32_t)__cvta_generic_to_shared(Bs[0]),
                        (uint32_t)__cvta_generic_to_shared(Bs[1]) };

    ACC_INIT;

    auto fillA = [&](uint32_t as, int ch) {
        int k0 = ch * BK;
#pragma unroll
        for (int j = 0; j < 2; j++) {
            int v = tid + 256 * j;
            int r = v >> 2, c8 = v & 3;
            int gr = m0 + r;
            if (gr >= M) gr = M - 1;
            int gc = k0 + c8 * 8;
            const __half* p = (gc < K1) ? A1 + (size_t)gr * K1 + gc
                                        : A2 + (size_t)gr * K2 + (gc - K1);
            cpa16(as + r * (STR * 2) + c8 * 16, p);
        }
    };

    fillA(asb[0], 0);
    fill_B(bsb[0], Wt, K, 0, n0, tid);
    CP_COMMIT;

#pragma unroll 1
    for (int ch = 0; ch < NCH; ch++) {
        int cur = ch & 1, nxt = cur ^ 1;
        if (ch + 1 < NCH) {
            fillA(asb[nxt], ch + 1);
            fill_B(bsb[nxt], Wt, K, ch + 1, n0, tid);
        }
        CP_COMMIT;
        CP_WAIT1;
        __syncthreads();
        mma_chunk(asb[cur], bsb[cur], acc, wm, wn, lane);
        __syncthreads();
    }

#pragma unroll
    for (int tm = 0; tm < 4; tm++) {
        int mr = m0 + wm * 64 + tm * 16 + (lane >> 2);
        float sc0 = 0.f, sc1 = 0.f;
        if (rowScale) {
            sc0 = rowScale[mr < M ? mr : M - 1];
            sc1 = rowScale[(mr + 8) < M ? (mr + 8) : M - 1];
        }
#pragma unroll
        for (int tn = 0; tn < 4; tn++) {
            int ncl = wn * 32 + tn * 8 + 2 * (lane & 3);
            float b0 = sBias[ncl], b1 = sBias[ncl + 1];
            float c0 = sBias2[ncl], c1 = sBias2[ncl + 1];
            float v0 = acc[tm][tn][0] + b0 + sc0 * c0;
            float v1 = acc[tm][tn][1] + b1 + sc0 * c1;
            float v2 = acc[tm][tn][2] + b0 + sc1 * c0;
            float v3 = acc[tm][tn][3] + b1 + sc1 * c1;
            if (doRelu) {
                v0 = fmaxf(v0, 0.f); v1 = fmaxf(v1, 0.f);
                v2 = fmaxf(v2, 0.f); v3 = fmaxf(v3, 0.f);
            }
            if (streamC) {
                if (mr < M)
                    stcs2(reinterpret_cast<__half2*>(Ch + (size_t)mr * ldc + n0 + ncl),
                          __floats2half2_rn(v0, v1));
                if (mr + 8 < M)
                    stcs2(reinterpret_cast<__half2*>(Ch + (size_t)(mr + 8) * ldc + n0 + ncl),
                          __floats2half2_rn(v2, v3));
            } else {
                if (mr < M)
                    *reinterpret_cast<__half2*>(Ch + (size_t)mr * ldc + n0 + ncl) =
                        __floats2half2_rn(v0, v1);
                if (mr + 8 < M)
                    *reinterpret_cast<__half2*>(Ch + (size_t)(mr + 8) * ldc + n0 + ncl) =
                        __floats2half2_rn(v2, v3);
            }
        }
    }
}

// ---------------- gather: S[n] = sum_{i in [eoff[n],eoff[n+1])} relu(P[n]+Q[src_csr[i]]+R[i])
__device__ __forceinline__ void acc8(float* acc, const float* p,
                                     uint4 qv, uint4 rv) {
    float2 q01 = __half22float2(*reinterpret_cast<__half2*>(&qv.x));
    float2 q23 = __half22float2(*reinterpret_cast<__half2*>(&qv.y));
    float2 q45 = __half22float2(*reinterpret_cast<__half2*>(&qv.z));
    float2 q67 = __half22float2(*reinterpret_cast<__half2*>(&qv.w));
    float2 r01 = __half22float2(*reinterpret_cast<__half2*>(&rv.x));
    float2 r23 = __half22float2(*reinterpret_cast<__half2*>(&rv.y));
    float2 r45 = __half22float2(*reinterpret_cast<__half2*>(&rv.z));
    float2 r67 = __half22float2(*reinterpret_cast<__half2*>(&rv.w));
    acc[0] += fmaxf(p[0] + q01.x + r01.x, 0.f);
    acc[1] += fmaxf(p[1] + q01.y + r01.y, 0.f);
    acc[2] += fmaxf(p[2] + q23.x + r23.x, 0.f);
    acc[3] += fmaxf(p[3] + q23.y + r23.y, 0.f);
    acc[4] += fmaxf(p[4] + q45.x + r45.x, 0.f);
    acc[5] += fmaxf(p[5] + q45.y + r45.y, 0.f);
    acc[6] += fmaxf(p[6] + q67.x + r67.x, 0.f);
    acc[7] += fmaxf(p[7] + q67.y + r67.y, 0.f);
}

__global__ void __launch_bounds__(256)
k_gather(const __half* __restrict__ PQ, const __half* __restrict__ Rh,
         __half* __restrict__ Sh)
{
    int n = blockIdx.x * 8 + (threadIdx.x >> 5);
    int lane = threadIdx.x & 31;
    if (n >= NN) return;
    int c0 = lane * 8;

    uint4 pv = *reinterpret_cast<const uint4*>(PQ + (size_t)n * 512 + c0);
    float p[8];
    {
        float2 t;
        t = __half22float2(*reinterpret_cast<__half2*>(&pv.x)); p[0] = t.x; p[1] = t.y;
        t = __half22float2(*reinterpret_cast<__half2*>(&pv.y)); p[2] = t.x; p[3] = t.y;
        t = __half22float2(*reinterpret_cast<__half2*>(&pv.z)); p[4] = t.x; p[5] = t.y;
        t = __half22float2(*reinterpret_cast<__half2*>(&pv.w)); p[6] = t.x; p[7] = t.y;
    }
    float acc[8];
#pragma unroll
    for (int j = 0; j < 8; j++) acc[j] = 0.f;

    int i = g_eoff[n], end = g_eoff[n + 1];
    for (; i + 2 <= end; i += 2) {
        int s0 = g_srccsr[i], s1 = g_srccsr[i + 1];
        uint4 q0 = *reinterpret_cast<const uint4*>(PQ + (size_t)s0 * 512 + 256 + c0);
        uint4 r0 = ldcs16(Rh + (size_t)i * HH + c0);
        uint4 q1 = *reinterpret_cast<const uint4*>(PQ + (size_t)s1 * 512 + 256 + c0);
        uint4 r1 = ldcs16(Rh + (size_t)(i + 1) * HH + c0);
        acc8(acc, p, q0, r0);
        acc8(acc, p, q1, r1);
    }
    if (i < end) {
        int s = g_srccsr[i];
        uint4 q = *reinterpret_cast<const uint4*>(PQ + (size_t)s * 512 + 256 + c0);
        uint4 r = ldcs16(Rh + (size_t)i * HH + c0);
        acc8(acc, p, q, r);
    }

    __half2* o = reinterpret_cast<__half2*>(Sh + (size_t)n * HH + c0);
    o[0] = __floats2half2_rn(acc[0], acc[1]);
    o[1] = __floats2half2_rn(acc[2], acc[3]);
    o[2] = __floats2half2_rn(acc[4], acc[5]);
    o[3] = __floats2half2_rn(acc[6], acc[7]);
}

// ---------------- pooling (sorted batch -> segment mean) ----------------
__global__ void k_pool(const __half* __restrict__ h) {
    int g = blockIdx.x, t = threadIdx.x;
    int r0 = g_goff[g], r1 = g_goff[g + 1];
    float acc = 0.f;
    for (int r = r0; r < r1; r++)
        acc += __half2float(h[(size_t)r * HH + t]);
    float cnt = (float)(r1 - r0);
    g_pool[g * HH + t] = acc / fmaxf(cnt, 1.0f);
}

// ---------------- head ----------------
__global__ void k_head1(const float* __restrict__ hw1, const float* __restrict__ hb1) {
    __shared__ float p[HH];
    int g = blockIdx.x;
    int t = threadIdx.x;
    p[t] = g_pool[g * HH + t];
    __syncthreads();
    float s = hb1[t];
    for (int k = 0; k < HH; k++) s += p[k] * hw1[k * HH + t];
    g_t1[g * HH + t] = fmaxf(s, 0.f);
}

__global__ void k_head2(const float* __restrict__ hw2, const float* __restrict__ hb2,
                        float* __restrict__ out) {
    __shared__ float q[HH];
    int g = blockIdx.x;
    int t = threadIdx.x;
    q[t] = g_t1[g * HH + t];
    q[t + 128] = g_t1[g * HH + t + 128];
    __syncthreads();
    float s = hb2[t];
    for (int k = 0; k < HH; k++) s += q[k] * hw2[k * OUTD + t];
    out[g * OUTD + t] = s;
}

// ---------------- launcher ----------------
extern "C" void kernel_launch(void* const* d_in, const int* in_sizes, int n_in,
                              void* d_out, int out_size)
{
    const float* x    = (const float*)d_in[0];
    const float* ea   = (const float*)d_in[1];
    const float* ew1  = (const float*)d_in[2];
    const float* eb1  = (const float*)d_in[3];
    const float* ew2  = (const float*)d_in[4];
    const float* eb2  = (const float*)d_in[5];
    const float* mw1  = (const float*)d_in[6];
    const float* mb1  = (const float*)d_in[7];
    const float* mw2  = (const float*)d_in[8];
    const float* mb2  = (const float*)d_in[9];
    const float* uw1  = (const float*)d_in[10];
    const float* ub1  = (const float*)d_in[11];
    const float* uw2  = (const float*)d_in[12];
    const float* ub2  = (const float*)d_in[13];
    const float* hw1  = (const float*)d_in[14];
    const float* hb1  = (const float*)d_in[15];
    const float* hw2  = (const float*)d_in[16];
    const float* hb2  = (const float*)d_in[17];
    const int*   eidx = (const int*)d_in[18];
    const int*   bat  = (const int*)d_in[19];
    float* out = (float*)d_out;

    void *p_h, *p_h2, *p_tmp, *p_Sh, *p_PQh, *p_Rh, *p_indeg, *p_ecnt, *p_gcnt;
    void *p_xh, *p_eacsr, *p_wemb1, *p_wemb2, *p_wpq, *p_w1c, *p_wfu, *p_wu2, *p_cvec;
    cudaGetSymbolAddress(&p_h,     g_h);
    cudaGetSymbolAddress(&p_h2,    g_h2);
    cudaGetSymbolAddress(&p_tmp,   g_tmp);
    cudaGetSymbolAddress(&p_Sh,    g_Sh);
    cudaGetSymbolAddress(&p_PQh,   g_PQh);
    cudaGetSymbolAddress(&p_Rh,    g_Rh);
    cudaGetSymbolAddress(&p_indeg, g_indeg);
    cudaGetSymbolAddress(&p_ecnt,  g_ecnt);
    cudaGetSymbolAddress(&p_gcnt,  g_gcnt);
    cudaGetSymbolAddress(&p_xh,    g_xh);
    cudaGetSymbolAddress(&p_eacsr, g_eacsr);
    cudaGetSymbolAddress(&p_wemb1, g_wemb1);
    cudaGetSymbolAddress(&p_wemb2, g_wemb2);
    cudaGetSymbolAddress(&p_wpq,   g_wpq);
    cudaGetSymbolAddress(&p_w1c,   g_w1c);
    cudaGetSymbolAddress(&p_wfu,   g_wfu);
    cudaGetSymbolAddress(&p_wu2,   g_wu2);
    cudaGetSymbolAddress(&p_cvec,  g_cvec);

    // CSR + indeg + permuted edge data + graph offsets
    k_detect<<<1, 256>>>(eidx);
    cudaMemsetAsync(p_ecnt, 0, NN * sizeof(int));
    cudaMemsetAsync(p_gcnt, 0, NG * sizeof(int));
    k_hist<<<(NE + 255) / 256, 256>>>(eidx);
    k_scan<<<1, 1024>>>();
    k_fillcsr<<<(NE + 255) / 256, 256>>>(eidx);
    k_permute<<<(NE * 16 + 255) / 256, 256>>>(ea, eidx);
    k_gcnt<<<(NN + 255) / 256, 256>>>(bat);
    k_goff<<<1, 1>>>();

    auto f2h = [&](const float* src, __half* dst, size_t n) {
        int n2 = (int)(n / 2);
        k_f2h<<<(n2 + 255) / 256, 256>>>((const float2*)src, (__half2*)dst, n2);
    };
    f2h(x, (__half*)p_xh, (size_t)NN * NFD);
    k_wt<<<(NFD * HH + 255) / 256, 256>>>(ew1, (__half*)p_wemb1, NFD, HH);
    k_wt<<<(HH * HH + 255) / 256, 256>>>(ew2, (__half*)p_wemb2, HH, HH);
    k_wt_mw1<<<dim3(((2 * HH + EFD) * HH + 255) / 256, NL), 256>>>(mw1);
    k_wt_uw2<<<dim3((HH * HH + 255) / 256, NL), 256>>>(uw2);
    k_w2u<<<dim3(16, 16, NL), dim3(16, 16)>>>(mw2, uw1);
    k_packfu<<<dim3((HH * 2 * HH + 255) / 256, NL), 256>>>(uw1);
    k_cvec<<<NL, HH>>>(mb2, uw1);

    dim3 gNode(157, 2);          // 20000 rows, N=256
    dim3 gPQ(157, 4);            // N=512
    dim3 gR(2500, 2);            // 320000 rows, N=256

    // embedder
    k_node<<<gNode, 256>>>((const __half*)p_xh, NFD, nullptr, 0,
                           (const __half*)p_wemb1, eb1, nullptr, nullptr,
                           (__half*)p_tmp, HH, NN, 1, 0);
    k_node<<<gNode, 256>>>((const __half*)p_tmp, HH, nullptr, 0,
                           (const __half*)p_wemb2, eb2, nullptr, nullptr,
                           (__half*)p_h, HH, NN, 0, 0);

    __half* hc = (__half*)p_h;
    __half* hn = (__half*)p_h2;

    for (int l = 0; l < NL; l++) {
        const __half* wpql = (const __half*)p_wpq + (size_t)l * 2 * HH * HH;
        const __half* w1cl = (const __half*)p_w1c + (size_t)l * HH * EFD;
        const __half* wful = (const __half*)p_wfu + (size_t)l * HH * 2 * HH;
        const __half* wu2l = (const __half*)p_wu2 + (size_t)l * HH * HH;
        const float*  cl   = (const float*)p_cvec + (size_t)l * HH;

        // PQ = h @ [W1a | W1b]   (fp16 out, ldc=512)
        k_node<<<gPQ, 256>>>(hc, HH, nullptr, 0, wpql, nullptr, nullptr, nullptr,
                             (__half*)p_PQh, 2 * HH, NN, 0, 0);
        // R = ea_csr @ W1c + b1  (fp16 out, CSR order, streaming stores)
        k_node<<<gR, 256>>>((const __half*)p_eacsr, EFD, nullptr, 0, w1cl,
                            mb1 + l * HH, nullptr, nullptr,
                            (__half*)p_Rh, HH, NE, 0, 1);
        // S[n] = sum_in relu(P[n]+Q[src]+R[i])  -> fp16
        k_gather<<<2500, 256>>>((const __half*)p_PQh, (const __half*)p_Rh,
                                (__half*)p_Sh);
        // upd1 = relu( h@uw1_top + S@W2u + ub1 + indeg*c )
        k_node<<<gNode, 256>>>(hc, HH, (const __half*)p_Sh, HH, wful,
                               ub1 + l * HH, cl, (const float*)p_indeg,
                               (__half*)p_tmp, HH, NN, 1, 0);
        // upd2
        k_node<<<gNode, 256>>>((const __half*)p_tmp, HH, nullptr, 0, wu2l,
                               ub2 + l * HH, nullptr, nullptr,
                               hn, HH, NN, 0, 0);
        __half* t = hc; hc = hn; hn = t;
    }

    k_pool<<<NG, HH>>>(hc);
    k_head1<<<NG, HH>>>(hw1, hb1);
    k_head2<<<NG, OUTD>>>(hw2, hb2, out);
}